// round 13
// baseline (speedup 1.0000x reference)
#include <cuda_runtime.h>
#include <cuda_bf16.h>
#include <cstdint>

// ---------------------------------------------------------------------------
// Problem constants
// ---------------------------------------------------------------------------
#define N_TOK 2048
#define DIM   1024
#define DFF   4096
#define HALF  2048
#define INNER 512
#define DEPTH 6
#define GDEPTH 2
#define VOCAB 32
#define WSZ   512
#define NHEAD 8
#define DHEAD 64
#define KSPLIT 2

// ---------------------------------------------------------------------------
// Scratch (device globals — no allocation allowed)
// ---------------------------------------------------------------------------
__device__ float g_x  [N_TOK * DIM];
__device__ float g_xn [N_TOK * DIM];
__device__ float g_qkv[N_TOK * 3 * INNER];
__device__ float g_h  [N_TOK * DFF];
__device__ float g_gt [N_TOK * HALF];
__device__ float g_tp [N_TOK * HALF];
__device__ float g_part[KSPLIT * N_TOK * NHEAD * 72];
// bf16 split buffers
__device__ __nv_bfloat16 g_xnhi[N_TOK * DIM],   g_xnlo[N_TOK * DIM];
__device__ __nv_bfloat16 g_hhi [N_TOK * DFF],   g_hlo [N_TOK * DFF];
__device__ __nv_bfloat16 g_athi[N_TOK * INNER], g_atlo[N_TOK * INNER];
__device__ __nv_bfloat16 g_tphi[N_TOK * HALF],  g_tplo[N_TOK * HALF];
__device__ __nv_bfloat16 g_g2hi[N_TOK * HALF],  g_g2lo[N_TOK * HALF];
__device__ __nv_bfloat16 g_swhi[N_TOK * N_TOK], g_swlo[N_TOK * N_TOK];
__device__ __nv_bfloat16 g_bhi [4 * 1024 * 1024], g_blo[4 * 1024 * 1024];

// ---------------------------------------------------------------------------
// Helpers
// ---------------------------------------------------------------------------
__device__ __forceinline__ float gelu_f(float x) {
    const float c = 0.7978845608028654f;
    float t = tanhf(c * (x + 0.044715f * x * x * x));
    return 0.5f * x * (1.0f + t);
}

__device__ __forceinline__ uint32_t s2u(const void* p) {
    uint32_t a;
    asm("{ .reg .u64 t; cvta.to.shared.u64 t, %1; cvt.u32.u64 %0, t; }"
        : "=r"(a) : "l"(p));
    return a;
}

#define CP_ASYNC16(dst, src) \
    asm volatile("cp.async.cg.shared.global [%0], [%1], 16;" :: "r"(dst), "l"(src))
#define CP_COMMIT() asm volatile("cp.async.commit_group;" ::: "memory")
#define CP_WAIT1()  asm volatile("cp.async.wait_group 1;" ::: "memory")
#define CP_WAIT0()  asm volatile("cp.async.wait_group 0;" ::: "memory")

#define LDSM4(r, addr) \
    asm volatile("ldmatrix.sync.aligned.m8n8.x4.shared.b16 {%0,%1,%2,%3}, [%4];" \
                 : "=r"((r)[0]), "=r"((r)[1]), "=r"((r)[2]), "=r"((r)[3]) : "r"(addr))

__device__ __forceinline__ void mma_bf16(float* c, const uint32_t* a, const uint32_t* b) {
    asm volatile(
        "mma.sync.aligned.m16n8k16.row.col.f32.bf16.bf16.f32 "
        "{%0,%1,%2,%3}, {%4,%5,%6,%7}, {%8,%9}, {%0,%1,%2,%3};"
        : "+f"(c[0]), "+f"(c[1]), "+f"(c[2]), "+f"(c[3])
        : "r"(a[0]), "r"(a[1]), "r"(a[2]), "r"(a[3]), "r"(b[0]), "r"(b[1]));
}

__device__ __forceinline__ uint32_t pack_bf2(float a, float b) {
    __nv_bfloat162 h = __floats2bfloat162_rn(a, b);
    return *(uint32_t*)&h;
}
__device__ __forceinline__ float bf16r(float v) {
    return __bfloat162float(__float2bfloat16(v));
}

// ---------------------------------------------------------------------------
// Embedding gather
// ---------------------------------------------------------------------------
__global__ void embed_kernel(const int* __restrict__ tok,
                             const float* __restrict__ emb,
                             float* __restrict__ x) {
    int row = blockIdx.x;
    int t = tok[row];
    const float4* src = (const float4*)(emb + (size_t)t * DIM);
    float4* dst = (float4*)(x + (size_t)row * DIM);
    for (int i = threadIdx.x; i < DIM / 4; i += blockDim.x) dst[i] = src[i];
}

// ---------------------------------------------------------------------------
// LayerNorm: optional fp32 out and/or bf16 hi/lo out.
// ---------------------------------------------------------------------------
__global__ void __launch_bounds__(256) ln_kernel(const float* __restrict__ src, int lds,
                                                 const float* __restrict__ gamma,
                                                 float* __restrict__ dstF,
                                                 __nv_bfloat16* __restrict__ hi,
                                                 __nv_bfloat16* __restrict__ lo,
                                                 int ldd, int D) {
    int row = blockIdx.x;
    const float* x = src + (size_t)row * lds;
    float s = 0.f, s2 = 0.f;
    for (int i = threadIdx.x; i < D; i += 256) {
        float v = x[i];
        s += v; s2 += v * v;
    }
    __shared__ float sh[64];
    #pragma unroll
    for (int o = 16; o; o >>= 1) {
        s  += __shfl_xor_sync(0xFFFFFFFFu, s,  o);
        s2 += __shfl_xor_sync(0xFFFFFFFFu, s2, o);
    }
    int warp = threadIdx.x >> 5, lane = threadIdx.x & 31;
    if (lane == 0) { sh[warp] = s; sh[32 + warp] = s2; }
    __syncthreads();
    if (warp == 0) {
        s  = (lane < 8) ? sh[lane]      : 0.f;
        s2 = (lane < 8) ? sh[32 + lane] : 0.f;
        #pragma unroll
        for (int o = 4; o; o >>= 1) {
            s  += __shfl_xor_sync(0xFFFFFFFFu, s,  o);
            s2 += __shfl_xor_sync(0xFFFFFFFFu, s2, o);
        }
        if (lane == 0) {
            float mean = s / D;
            float var  = s2 / D - mean * mean;
            sh[0] = mean;
            sh[1] = rsqrtf(var + 1e-5f);
        }
    }
    __syncthreads();
    float mean = sh[0], rstd = sh[1];
    for (int i = threadIdx.x * 2; i < D; i += 512) {
        float v0 = (x[i]     - mean) * rstd * gamma[i];
        float v1 = (x[i + 1] - mean) * rstd * gamma[i + 1];
        size_t o = (size_t)row * ldd + i;
        if (dstF) { dstF[o] = v0; dstF[o + 1] = v1; }
        if (hi) {
            float h0 = bf16r(v0), h1 = bf16r(v1);
            *(uint32_t*)(hi + o) = pack_bf2(h0, h1);
            *(uint32_t*)(lo + o) = pack_bf2(v0 - h0, v1 - h1);
        }
    }
}

// ---------------------------------------------------------------------------
// Split A (fp32 -> bf16 hi/lo) with tril mask — only used for g_sw.
// ---------------------------------------------------------------------------
__global__ void __launch_bounds__(256) splitA_k(const float* __restrict__ A,
                                                __nv_bfloat16* __restrict__ hi,
                                                __nv_bfloat16* __restrict__ lo,
                                                int MK, int K, int tril) {
    int i4 = (blockIdx.x * 256 + threadIdx.x) * 4;
    if (i4 >= MK) return;
    float4 v = *(const float4*)(A + i4);
    float vv[4] = {v.x, v.y, v.z, v.w};
    if (tril) {
        int m = i4 / K, k = i4 - m * K;
        #pragma unroll
        for (int e = 0; e < 4; e++)
            if (k + e > m) vv[e] = 0.f;
    }
    float hf[4];
    #pragma unroll
    for (int e = 0; e < 4; e++) hf[e] = bf16r(vv[e]);
    uint2 ho, lo2;
    ho.x  = pack_bf2(hf[0], hf[1]); ho.y  = pack_bf2(hf[2], hf[3]);
    lo2.x = pack_bf2(vv[0] - hf[0], vv[1] - hf[1]);
    lo2.y = pack_bf2(vv[2] - hf[2], vv[3] - hf[3]);
    *(uint2*)(hi + i4) = ho;
    *(uint2*)(lo + i4) = lo2;
}

// ---------------------------------------------------------------------------
// Transpose + split B: B[K][N] fp32 -> Bt hi/lo bf16 [N][K]
// ---------------------------------------------------------------------------
__global__ void __launch_bounds__(256) tspB_k(const float* __restrict__ B,
                                              __nv_bfloat16* __restrict__ hi,
                                              __nv_bfloat16* __restrict__ lo,
                                              int K, int N) {
    __shared__ float sh[32][33];
    int nt = blockIdx.x * 32, kt = blockIdx.y * 32;
    int tx = threadIdx.x & 31, ty = threadIdx.x >> 5;
    #pragma unroll
    for (int j = 0; j < 32; j += 8)
        sh[ty + j][tx] = B[(size_t)(kt + ty + j) * N + nt + tx];
    __syncthreads();
    #pragma unroll
    for (int j = 0; j < 32; j += 8) {
        float v = sh[tx][ty + j];
        float h = bf16r(v);
        size_t o = (size_t)(nt + ty + j) * K + kt + tx;
        hi[o] = __float2bfloat16(h);
        lo[o] = __float2bfloat16(v - h);
    }
}

// ---------------------------------------------------------------------------
// Split-bf16 3-term tensor-core GEMM, templated on BM (64 or 128 M-tile).
// BM=64: 3 CTAs/SM; BM=128: 2 CTAs/SM. Term-major mma ordering.
// ---------------------------------------------------------------------------
enum { F_BIAS = 1, F_GELU = 2, F_RES = 4, F_MULX = 16, F_ROWB = 32, F_SPLIT = 64 };

#define BTILE_BYTES 10240   // 128 rows x 80B

template <int FLAGS, int BM>
__global__ void __launch_bounds__(256, (BM == 64) ? 3 : 2) gemm_bf3(
    const __nv_bfloat16* __restrict__ Ahi, const __nv_bfloat16* __restrict__ Alo,
    const __nv_bfloat16* __restrict__ Bhi, const __nv_bfloat16* __restrict__ Blo,
    const float* __restrict__ bias, const float* __restrict__ rbias,
    const float* __restrict__ Xm, int ldx,
    const float* __restrict__ resid,
    float* __restrict__ C,
    __nv_bfloat16* __restrict__ Chi, __nv_bfloat16* __restrict__ Clo,
    int M, int N, int K) {

    constexpr int ATILE = BM * 80;
    constexpr int STAGE = 2 * ATILE + 2 * BTILE_BYTES;
    constexpr int UP    = (BM == 128) ? 4 : 2;   // 16-col uptiles per warp

    extern __shared__ char dsm[];
    const uint32_t smem_base = s2u(dsm);

    const int tid  = threadIdx.x;
    const int wid  = tid >> 5;
    const int lane = tid & 31;
    const int wm   = (BM == 128) ? (wid >> 1) : (wid & 1);
    const int wn   = (BM == 128) ? (wid & 1)  : (wid >> 1);
    const int bm = blockIdx.y * BM, bn = blockIdx.x * 128;

    float acc[2][2 * UP][4];
    #pragma unroll
    for (int i = 0; i < 2; i++)
        #pragma unroll
        for (int j = 0; j < 2 * UP; j++)
            #pragma unroll
            for (int e = 0; e < 4; e++) acc[i][j][e] = 0.f;

    const __nv_bfloat16* bases[4] = {
        Ahi + (size_t)bm * K, Alo + (size_t)bm * K,
        Bhi + (size_t)bn * K, Blo + (size_t)bn * K };

    const int mi  = lane >> 3;
    const int lr8 = lane & 7;
    const int a_off = ((mi & 1) * 8 + lr8) * 80 + (mi >> 1) * 16;
    const int b_off = ((mi >> 1) * 8 + lr8) * 80 + (mi & 1) * 16;

    const int nK = K >> 5;

    #define LOAD_STAGE(s, kt) do {                                             \
        uint32_t sb_ = smem_base + (s) * STAGE;                                \
        int kc_ = (kt) << 5;                                                   \
        _Pragma("unroll")                                                      \
        for (int t = 0; t < (2 * BM * 4) / 256; t++) {                         \
            int w = t * 256 + tid;                                             \
            int tile = w / (BM * 4);                                           \
            int row = (w % (BM * 4)) >> 2, ch = w & 3;                         \
            const char* src = (const char*)(bases[tile] + (size_t)row * K + kc_ + ch * 8); \
            uint32_t dst = sb_ + tile * ATILE + row * 80 + ch * 16;            \
            CP_ASYNC16(dst, src);                                              \
        }                                                                      \
        _Pragma("unroll")                                                      \
        for (int t = 0; t < 4; t++) {                                          \
            int w = t * 256 + tid;                                             \
            int bt = w >> 9;                                                   \
            int row = (w & 511) >> 2, ch = w & 3;                              \
            const char* src = (const char*)(bases[2 + bt] + (size_t)row * K + kc_ + ch * 8); \
            uint32_t dst = sb_ + 2 * ATILE + bt * BTILE_BYTES + row * 80 + ch * 16; \
            CP_ASYNC16(dst, src);                                              \
        }                                                                      \
        CP_COMMIT();                                                           \
    } while (0)

    LOAD_STAGE(0, 0);

    for (int kt = 0; kt < nK; kt++) {
        int s = kt & 1;
        if (kt + 1 < nK) {
            LOAD_STAGE(s ^ 1, kt + 1);
            CP_WAIT1();
        } else {
            CP_WAIT0();
        }
        __syncthreads();

        uint32_t TAh = smem_base + s * STAGE;
        uint32_t TAl = TAh + ATILE;
        uint32_t TBh = TAh + 2 * ATILE;
        uint32_t TBl = TBh + BTILE_BYTES;

        #pragma unroll
        for (int ks = 0; ks < 2; ks++) {
            uint32_t ah[2][4], al_[2][4];
            #pragma unroll
            for (int mt = 0; mt < 2; mt++) {
                int rb = (wm * 32 + mt * 16) * 80 + ks * 32;
                LDSM4(ah[mt],  TAh + rb + a_off);
                LDSM4(al_[mt], TAl + rb + a_off);
            }
            uint32_t bh[UP][4], bl[UP][4];
            #pragma unroll
            for (int up = 0; up < UP; up++) {
                int rb = (wn * UP * 16 + up * 16) * 80 + ks * 32;
                LDSM4(bh[up], TBh + rb + b_off);
                LDSM4(bl[up], TBl + rb + b_off);
            }
            #pragma unroll
            for (int term = 0; term < 3; term++) {
                #pragma unroll
                for (int mt = 0; mt < 2; mt++) {
                    const uint32_t* A_ = (term == 2) ? al_[mt] : ah[mt];
                    #pragma unroll
                    for (int up = 0; up < UP; up++) {
                        const uint32_t* B_ = (term == 1) ? bl[up] : bh[up];
                        mma_bf16(acc[mt][2 * up],     A_, &B_[0]);
                        mma_bf16(acc[mt][2 * up + 1], A_, &B_[2]);
                    }
                }
            }
        }
        __syncthreads();
    }

    const int r0 = bm + wm * 32 + (lane >> 2);
    const int cb = bn + wn * (UP * 16) + (lane & 3) * 2;
    #pragma unroll
    for (int mt = 0; mt < 2; mt++) {
        #pragma unroll
        for (int nt = 0; nt < 2 * UP; nt++) {
            float* a4 = acc[mt][nt];
            int gm = r0 + mt * 16;
            int gn = cb + nt * 8;
            float vv[4];
            #pragma unroll
            for (int e = 0; e < 4; e++) {
                int rr = gm + (e >> 1) * 8;
                int cc = gn + (e & 1);
                float v = a4[e];
                if (FLAGS & F_BIAS) v += bias[cc];
                if (FLAGS & F_ROWB) v += rbias[rr];
                if (FLAGS & F_GELU) v = gelu_f(v);
                if (FLAGS & F_MULX) v *= Xm[(size_t)rr * ldx + cc];
                if (FLAGS & F_RES)  v += resid[(size_t)rr * N + cc];
                vv[e] = v;
            }
            size_t o0 = (size_t)gm * N + gn;
            size_t o1 = (size_t)(gm + 8) * N + gn;
            *(float2*)(C + o0) = make_float2(vv[0], vv[1]);
            *(float2*)(C + o1) = make_float2(vv[2], vv[3]);
            if (FLAGS & F_SPLIT) {
                float h0 = bf16r(vv[0]), h1 = bf16r(vv[1]);
                float h2 = bf16r(vv[2]), h3 = bf16r(vv[3]);
                *(uint32_t*)(Chi + o0) = pack_bf2(h0, h1);
                *(uint32_t*)(Chi + o1) = pack_bf2(h2, h3);
                *(uint32_t*)(Clo + o0) = pack_bf2(vv[0] - h0, vv[1] - h1);
                *(uint32_t*)(Clo + o1) = pack_bf2(vv[2] - h2, vv[3] - h3);
            }
        }
    }
}

// ---------------------------------------------------------------------------
// Exact fp32 SIMT GEMM for the head (N=32)
// ---------------------------------------------------------------------------
__global__ void __launch_bounds__(256) gemm_head(
    const float* __restrict__ A, const float* __restrict__ B,
    const float* __restrict__ bias, float* __restrict__ C,
    int M, int N, int K) {
    __shared__ float As[16][128];
    __shared__ float Bs[16][32];
    const int tid = threadIdx.x;
    const int bm = blockIdx.y * 128;
    const int r = tid >> 1;
    const int cp = (tid & 1) * 16;
    float acc[16];
    #pragma unroll
    for (int j = 0; j < 16; j++) acc[j] = 0.f;

    const int a_row = tid >> 2, a_col = (tid & 3) << 2;
    const int b_row = tid >> 3, b_col = (tid & 7) << 2;

    for (int kt = 0; kt < K; kt += 16) {
        #pragma unroll
        for (int rr = 0; rr < 2; rr++) {
            int lm = a_row + rr * 64;
            float4 v = *(const float4*)(A + (size_t)(bm + lm) * K + kt + a_col);
            As[a_col + 0][lm] = v.x; As[a_col + 1][lm] = v.y;
            As[a_col + 2][lm] = v.z; As[a_col + 3][lm] = v.w;
        }
        if (b_row < 16) {
            float4 v = *(const float4*)(B + (size_t)(kt + b_row) * N + b_col);
            *(float4*)&Bs[b_row][b_col] = v;
        }
        __syncthreads();
        #pragma unroll
        for (int kk = 0; kk < 16; kk++) {
            float a = As[kk][r];
            #pragma unroll
            for (int j = 0; j < 16; j++) acc[j] += a * Bs[kk][cp + j];
        }
        __syncthreads();
    }
    #pragma unroll
    for (int j = 0; j < 16; j++)
        C[(size_t)(bm + r) * N + cp + j] = acc[j] + bias[cp + j];
}

// ---------------------------------------------------------------------------
// Local windowed attention, split-K into KSPLIT=2 halves (round-7 mapping).
// grid ((rc*2+half) : 8, w : 4, h : 8) = 256 blocks, 128 thr.
// ---------------------------------------------------------------------------
__global__ void __launch_bounds__(128) attn_part(const float* __restrict__ qkv,
                                                 float* __restrict__ part) {
    const int h    = blockIdx.z;
    const int w    = blockIdx.y;
    const int rc   = blockIdx.x >> 1;
    const int half = blockIdx.x & 1;
    const int i  = rc * 128 + threadIdx.x;
    const int t  = w * WSZ + i;

    float q[64];
    {
        const float4* qp = (const float4*)(qkv + (size_t)t * (3 * INNER) + h * DHEAD);
        #pragma unroll
        for (int d = 0; d < 16; d++) {
            float4 v = qp[d];
            q[4 * d + 0] = v.x * 0.125f;
            q[4 * d + 1] = v.y * 0.125f;
            q[4 * d + 2] = v.z * 0.125f;
            q[4 * d + 3] = v.w * 0.125f;
        }
    }
    float o[64];
    #pragma unroll
    for (int d = 0; d < 64; d++) o[d] = 0.f;
    float m = -1e30f, l = 0.f;

    __shared__ float Ks[32][68];
    __shared__ float Vs[32][68];

    const int lr = threadIdx.x >> 2;
    const int lc = (threadIdx.x & 3) * 16;

    const int n  = min(32, rc * 4 + 20);
    const int c0 = half ? (n >> 1) : 0;
    const int c1 = half ? n : (n >> 1);

    for (int c = c0; c < c1; c++) {
        int j0 = c * 32;
        int tok = (w - 1) * WSZ + j0 + lr;
        const float* kp = qkv + (size_t)tok * (3 * INNER) + INNER + h * DHEAD + lc;
        const float* vp = kp + INNER;
        #pragma unroll
        for (int e = 0; e < 4; e++) {
            float4 kv = make_float4(0.f, 0.f, 0.f, 0.f);
            float4 vv = make_float4(0.f, 0.f, 0.f, 0.f);
            if (tok >= 0) {
                kv = *(const float4*)(kp + 4 * e);
                vv = *(const float4*)(vp + 4 * e);
            }
            *(float4*)&Ks[lr][lc + 4 * e] = kv;
            *(float4*)&Vs[lr][lc + 4 * e] = vv;
        }
        __syncthreads();

        float s[32];
        float mnew = m;
        #pragma unroll
        for (int jj = 0; jj < 32; jj++) {
            float sv = -1e30f;
            if (j0 + jj <= i + WSZ) {
                sv = 0.f;
                #pragma unroll
                for (int d = 0; d < 64; d++) sv += q[d] * Ks[jj][d];
            }
            s[jj] = sv;
            mnew = fmaxf(mnew, sv);
        }
        float corr = __expf(m - mnew);
        l *= corr;
        #pragma unroll
        for (int d = 0; d < 64; d++) o[d] *= corr;
        #pragma unroll
        for (int jj = 0; jj < 32; jj++) {
            float p = __expf(s[jj] - mnew);
            l += p;
            #pragma unroll
            for (int d = 0; d < 64; d++) o[d] += p * Vs[jj][d];
        }
        m = mnew;
        __syncthreads();
    }

    float* pp = part + ((size_t)half * N_TOK * NHEAD + (size_t)t * NHEAD + h) * 72;
    #pragma unroll
    for (int d = 0; d < 16; d++)
        *(float4*)(pp + 4 * d) = make_float4(o[4*d], o[4*d+1], o[4*d+2], o[4*d+3]);
    pp[64] = m;
    pp[65] = l;
}

// ---------------------------------------------------------------------------
// Combine KSPLIT partials; emit ATT as bf16 hi/lo directly.
// ---------------------------------------------------------------------------
__global__ void __launch_bounds__(128) attn_comb(const float* __restrict__ part,
                                                 __nv_bfloat16* __restrict__ athi,
                                                 __nv_bfloat16* __restrict__ atlo) {
    int idx = blockIdx.x * 128 + threadIdx.x;
    int t = idx >> 3, h = idx & 7;
    const float* p[KSPLIT];
    float mm[KSPLIT], ll[KSPLIT];
    float M = -1e30f;
    #pragma unroll
    for (int s = 0; s < KSPLIT; s++) {
        p[s] = part + ((size_t)s * N_TOK * NHEAD + (size_t)t * NHEAD + h) * 72;
        mm[s] = p[s][64];
        ll[s] = p[s][65];
        M = fmaxf(M, mm[s]);
    }
    float wts[KSPLIT], L = 0.f;
    #pragma unroll
    for (int s = 0; s < KSPLIT; s++) {
        wts[s] = __expf(mm[s] - M);
        L += ll[s] * wts[s];
    }
    float inv = 1.f / L;
    uint32_t* oh = (uint32_t*)(athi + (size_t)t * INNER + h * DHEAD);
    uint32_t* ol = (uint32_t*)(atlo + (size_t)t * INNER + h * DHEAD);
    #pragma unroll
    for (int d = 0; d < 64; d += 2) {
        float a = 0.f, b = 0.f;
        #pragma unroll
        for (int s = 0; s < KSPLIT; s++) {
            a += p[s][d]     * wts[s];
            b += p[s][d + 1] * wts[s];
        }
        a *= inv; b *= inv;
        float ha = bf16r(a), hb = bf16r(b);
        oh[d >> 1] = pack_bf2(ha, hb);
        ol[d >> 1] = pack_bf2(a - ha, b - hb);
    }
}

// ---------------------------------------------------------------------------
// Host-side dispatch
// ---------------------------------------------------------------------------
static __nv_bfloat16 *BHI, *BLO;

#define SMEM64  (2 * (2 * 64  * 80 + 2 * BTILE_BYTES))   // 61440
#define SMEM128 (2 * (2 * 128 * 80 + 2 * BTILE_BYTES))   // 81920

static void gemm(int flags, const __nv_bfloat16* Ahi, const __nv_bfloat16* Alo,
                 const float* B, const float* bias, const float* rbias,
                 const float* Xm, int ldx, const float* resid,
                 float* C, __nv_bfloat16* Chi, __nv_bfloat16* Clo,
                 int M, int N, int K) {
    tspB_k<<<dim3(N / 32, K / 32), 256>>>(B, BHI, BLO, K, N);
    if (N <= 1536) {
        dim3 grid(N / 128, M / 64);
        switch (flags) {
            case 0:
                gemm_bf3<0, 64><<<grid, 256, SMEM64>>>(Ahi, Alo, BHI, BLO, bias, rbias, Xm, ldx, resid, C, Chi, Clo, M, N, K); break;
            case F_BIAS | F_RES:
                gemm_bf3<F_BIAS | F_RES, 64><<<grid, 256, SMEM64>>>(Ahi, Alo, BHI, BLO, bias, rbias, Xm, ldx, resid, C, Chi, Clo, M, N, K); break;
        }
    } else {
        dim3 grid(N / 128, M / 128);
        switch (flags) {
            case F_BIAS | F_GELU:
                gemm_bf3<F_BIAS | F_GELU, 128><<<grid, 256, SMEM128>>>(Ahi, Alo, BHI, BLO, bias, rbias, Xm, ldx, resid, C, Chi, Clo, M, N, K); break;
            case F_BIAS | F_GELU | F_SPLIT:
                gemm_bf3<F_BIAS | F_GELU | F_SPLIT, 128><<<grid, 256, SMEM128>>>(Ahi, Alo, BHI, BLO, bias, rbias, Xm, ldx, resid, C, Chi, Clo, M, N, K); break;
            case F_ROWB | F_MULX | F_SPLIT:
                gemm_bf3<F_ROWB | F_MULX | F_SPLIT, 128><<<grid, 256, SMEM128>>>(Ahi, Alo, BHI, BLO, bias, rbias, Xm, ldx, resid, C, Chi, Clo, M, N, K); break;
            case F_BIAS | F_SPLIT:
                gemm_bf3<F_BIAS | F_SPLIT, 128><<<grid, 256, SMEM128>>>(Ahi, Alo, BHI, BLO, bias, rbias, Xm, ldx, resid, C, Chi, Clo, M, N, K); break;
        }
    }
}

extern "C" void kernel_launch(void* const* d_in, const int* in_sizes, int n_in,
                              void* d_out, int out_size) {
    (void)in_sizes; (void)n_in;
    const int*   tokens   = (const int*)  d_in[0];
    const float* embed    = (const float*)d_in[1];
    const float* attn_ln  = (const float*)d_in[2];
    const float* attn_qkv = (const float*)d_in[3];
    const float* attn_ow  = (const float*)d_in[4];
    const float* attn_ob  = (const float*)d_in[5];
    const float* ff_ln    = (const float*)d_in[6];
    const float* ff_w1    = (const float*)d_in[7];
    const float* ff_b1    = (const float*)d_in[8];
    const float* ff_w2    = (const float*)d_in[9];
    const float* ff_b2    = (const float*)d_in[10];
    const float* gl_ln    = (const float*)d_in[11];
    const float* g_win    = (const float*)d_in[12];
    const float* g_bin    = (const float*)d_in[13];
    const float* g_sln    = (const float*)d_in[14];
    const float* g_sw     = (const float*)d_in[15];
    const float* g_sb     = (const float*)d_in[16];
    const float* g_sow    = (const float*)d_in[17];
    const float* g_sob    = (const float*)d_in[18];
    const float* g_pow    = (const float*)d_in[19];
    const float* g_pob    = (const float*)d_in[20];
    const float* fin_ln   = (const float*)d_in[21];
    const float* head_w   = (const float*)d_in[22];
    const float* head_b   = (const float*)d_in[23];
    float* out = (float*)d_out;
    (void)out_size;

    float *X, *XN, *QKV, *H, *GT, *TP, *PART;
    __nv_bfloat16 *XNHI, *XNLO, *HHI, *HLO, *ATHI, *ATLO, *TPHI, *TPLO,
                  *G2HI, *G2LO, *SWHI, *SWLO;
    cudaGetSymbolAddress((void**)&X,    g_x);
    cudaGetSymbolAddress((void**)&XN,   g_xn);
    cudaGetSymbolAddress((void**)&QKV,  g_qkv);
    cudaGetSymbolAddress((void**)&H,    g_h);
    cudaGetSymbolAddress((void**)&GT,   g_gt);
    cudaGetSymbolAddress((void**)&TP,   g_tp);
    cudaGetSymbolAddress((void**)&PART, g_part);
    cudaGetSymbolAddress((void**)&XNHI, g_xnhi);
    cudaGetSymbolAddress((void**)&XNLO, g_xnlo);
    cudaGetSymbolAddress((void**)&HHI,  g_hhi);
    cudaGetSymbolAddress((void**)&HLO,  g_hlo);
    cudaGetSymbolAddress((void**)&ATHI, g_athi);
    cudaGetSymbolAddress((void**)&ATLO, g_atlo);
    cudaGetSymbolAddress((void**)&TPHI, g_tphi);
    cudaGetSymbolAddress((void**)&TPLO, g_tplo);
    cudaGetSymbolAddress((void**)&G2HI, g_g2hi);
    cudaGetSymbolAddress((void**)&G2LO, g_g2lo);
    cudaGetSymbolAddress((void**)&SWHI, g_swhi);
    cudaGetSymbolAddress((void**)&SWLO, g_swlo);
    cudaGetSymbolAddress((void**)&BHI,  g_bhi);
    cudaGetSymbolAddress((void**)&BLO,  g_blo);

    cudaFuncSetAttribute((const void*)gemm_bf3<0, 64>, cudaFuncAttributeMaxDynamicSharedMemorySize, SMEM64);
    cudaFuncSetAttribute((const void*)gemm_bf3<F_BIAS | F_RES, 64>, cudaFuncAttributeMaxDynamicSharedMemorySize, SMEM64);
    cudaFuncSetAttribute((const void*)gemm_bf3<F_BIAS | F_GELU, 128>, cudaFuncAttributeMaxDynamicSharedMemorySize, SMEM128);
    cudaFuncSetAttribute((const void*)gemm_bf3<F_BIAS | F_GELU | F_SPLIT, 128>, cudaFuncAttributeMaxDynamicSharedMemorySize, SMEM128);
    cudaFuncSetAttribute((const void*)gemm_bf3<F_ROWB | F_MULX | F_SPLIT, 128>, cudaFuncAttributeMaxDynamicSharedMemorySize, SMEM128);
    cudaFuncSetAttribute((const void*)gemm_bf3<F_BIAS | F_SPLIT, 128>, cudaFuncAttributeMaxDynamicSharedMemorySize, SMEM128);

    embed_kernel<<<N_TOK, 256>>>(tokens, embed, X);

    for (int l = 0; l < DEPTH; l++) {
        const float* al = attn_ln  + (size_t)l * DIM;
        const float* aq = attn_qkv + (size_t)l * DIM * 3 * INNER;
        const float* aw = attn_ow  + (size_t)l * INNER * DIM;
        const float* ab = attn_ob  + (size_t)l * DIM;
        const float* fl = ff_ln    + (size_t)l * DIM;
        const float* f1 = ff_w1    + (size_t)l * DIM * DFF;
        const float* b1 = ff_b1    + (size_t)l * DFF;
        const float* f2 = ff_w2    + (size_t)l * DFF * DIM;
        const float* b2 = ff_b2    + (size_t)l * DIM;

        ln_kernel<<<N_TOK, 256>>>(X, DIM, al, nullptr, XNHI, XNLO, DIM, DIM);
        gemm(0, XNHI, XNLO, aq, nullptr, nullptr, nullptr, 0, nullptr,
             QKV, nullptr, nullptr, N_TOK, 3 * INNER, DIM);
        attn_part<<<dim3(4 * KSPLIT, 4, NHEAD), 128>>>(QKV, PART);
        attn_comb<<<128, 128>>>(PART, ATHI, ATLO);
        gemm(F_BIAS | F_RES, ATHI, ATLO, aw, ab, nullptr, nullptr, 0, X,
             X, nullptr, nullptr, N_TOK, DIM, INNER);

        ln_kernel<<<N_TOK, 256>>>(X, DIM, fl, nullptr, XNHI, XNLO, DIM, DIM);
        gemm(F_BIAS | F_GELU | F_SPLIT, XNHI, XNLO, f1, b1, nullptr, nullptr, 0, nullptr,
             H, HHI, HLO, N_TOK, DFF, DIM);
        gemm(F_BIAS | F_RES, HHI, HLO, f2, b2, nullptr, nullptr, 0, X,
             X, nullptr, nullptr, N_TOK, DIM, DFF);
    }

    for (int g = 0; g < GDEPTH; g++) {
        const float* gl  = gl_ln + (size_t)g * DIM;
        const float* wi  = g_win + (size_t)g * DIM * DFF;
        const float* bi  = g_bin + (size_t)g * DFF;
        const float* sl  = g_sln + (size_t)g * HALF;
        const float* sw  = g_sw  + (size_t)g * N_TOK * N_TOK;
        const float* sb  = g_sb  + (size_t)g * N_TOK;
        const float* so  = g_sow + (size_t)g * HALF * HALF;
        const float* sob = g_sob + (size_t)g * HALF;
        const float* po  = g_pow + (size_t)g * HALF * DIM;
        const float* pob = g_pob + (size_t)g * DIM;

        ln_kernel<<<N_TOK, 256>>>(X, DIM, gl, nullptr, XNHI, XNLO, DIM, DIM);
        gemm(F_BIAS | F_GELU, XNHI, XNLO, wi, bi, nullptr, nullptr, 0, nullptr,
             H, nullptr, nullptr, N_TOK, DFF, DIM);
        ln_kernel<<<N_TOK, 256>>>(H + HALF, DFF, sl, GT, nullptr, nullptr, HALF, HALF);
        splitA_k<<<(N_TOK * N_TOK / 4 + 255) / 256, 256>>>(sw, SWHI, SWLO,
                                                           N_TOK * N_TOK, N_TOK, 1);
        gemm(F_ROWB | F_MULX | F_SPLIT, SWHI, SWLO, GT, nullptr, sb, H, DFF, nullptr,
             TP, TPHI, TPLO, N_TOK, HALF, N_TOK);
        gemm(F_BIAS | F_SPLIT, TPHI, TPLO, so, sob, nullptr, nullptr, 0, nullptr,
             GT, G2HI, G2LO, N_TOK, HALF, HALF);
        gemm(F_BIAS | F_RES, G2HI, G2LO, po, pob, nullptr, nullptr, 0, X,
             X, nullptr, nullptr, N_TOK, DIM, HALF);
    }

    ln_kernel<<<N_TOK, 256>>>(X, DIM, fin_ln, XN, nullptr, nullptr, DIM, DIM);
    gemm_head<<<dim3(1, N_TOK / 128), 256>>>(XN, head_w, head_b, out, N_TOK, VOCAB, DIM);
}

// round 14
// speedup vs baseline: 1.1687x; 1.1687x over previous
#include <cuda_runtime.h>
#include <cuda_bf16.h>
#include <cstdint>

// ---------------------------------------------------------------------------
// Problem constants
// ---------------------------------------------------------------------------
#define N_TOK 2048
#define DIM   1024
#define DFF   4096
#define HALF  2048
#define INNER 512
#define DEPTH 6
#define GDEPTH 2
#define VOCAB 32
#define WSZ   512
#define NHEAD 8
#define DHEAD 64

// ---------------------------------------------------------------------------
// Scratch (device globals — no allocation allowed)
// ---------------------------------------------------------------------------
__device__ float g_x  [N_TOK * DIM];
__device__ float g_xn [N_TOK * DIM];
__device__ float g_qkv[N_TOK * 3 * INNER];
__device__ float g_h  [N_TOK * DFF];
__device__ float g_gt [N_TOK * HALF];
__device__ float g_tp [N_TOK * HALF];
// bf16 split buffers
__device__ __nv_bfloat16 g_xnhi[N_TOK * DIM],   g_xnlo[N_TOK * DIM];
__device__ __nv_bfloat16 g_hhi [N_TOK * DFF],   g_hlo [N_TOK * DFF];
__device__ __nv_bfloat16 g_athi[N_TOK * INNER], g_atlo[N_TOK * INNER];
__device__ __nv_bfloat16 g_tphi[N_TOK * HALF],  g_tplo[N_TOK * HALF];
__device__ __nv_bfloat16 g_g2hi[N_TOK * HALF],  g_g2lo[N_TOK * HALF];
__device__ __nv_bfloat16 g_swhi[N_TOK * N_TOK], g_swlo[N_TOK * N_TOK];
__device__ __nv_bfloat16 g_bhi [4 * 1024 * 1024], g_blo[4 * 1024 * 1024];

// ---------------------------------------------------------------------------
// Helpers
// ---------------------------------------------------------------------------
__device__ __forceinline__ float gelu_f(float x) {
    const float c = 0.7978845608028654f;
    float t = tanhf(c * (x + 0.044715f * x * x * x));
    return 0.5f * x * (1.0f + t);
}

__device__ __forceinline__ uint32_t s2u(const void* p) {
    uint32_t a;
    asm("{ .reg .u64 t; cvta.to.shared.u64 t, %1; cvt.u32.u64 %0, t; }"
        : "=r"(a) : "l"(p));
    return a;
}

#define CP_ASYNC16(dst, src) \
    asm volatile("cp.async.cg.shared.global [%0], [%1], 16;" :: "r"(dst), "l"(src))
#define CP_COMMIT() asm volatile("cp.async.commit_group;" ::: "memory")
#define CP_WAIT1()  asm volatile("cp.async.wait_group 1;" ::: "memory")
#define CP_WAIT0()  asm volatile("cp.async.wait_group 0;" ::: "memory")

#define LDSM4(r, addr) \
    asm volatile("ldmatrix.sync.aligned.m8n8.x4.shared.b16 {%0,%1,%2,%3}, [%4];" \
                 : "=r"((r)[0]), "=r"((r)[1]), "=r"((r)[2]), "=r"((r)[3]) : "r"(addr))

#define LDSM4T(r, addr) \
    asm volatile("ldmatrix.sync.aligned.m8n8.x4.trans.shared.b16 {%0,%1,%2,%3}, [%4];" \
                 : "=r"((r)[0]), "=r"((r)[1]), "=r"((r)[2]), "=r"((r)[3]) : "r"(addr))

__device__ __forceinline__ void mma_bf16(float* c, const uint32_t* a, const uint32_t* b) {
    asm volatile(
        "mma.sync.aligned.m16n8k16.row.col.f32.bf16.bf16.f32 "
        "{%0,%1,%2,%3}, {%4,%5,%6,%7}, {%8,%9}, {%0,%1,%2,%3};"
        : "+f"(c[0]), "+f"(c[1]), "+f"(c[2]), "+f"(c[3])
        : "r"(a[0]), "r"(a[1]), "r"(a[2]), "r"(a[3]), "r"(b[0]), "r"(b[1]));
}

__device__ __forceinline__ uint32_t pack_bf2(float a, float b) {
    __nv_bfloat162 h = __floats2bfloat162_rn(a, b);
    return *(uint32_t*)&h;
}
__device__ __forceinline__ float bf16r(float v) {
    return __bfloat162float(__float2bfloat16(v));
}

// ---------------------------------------------------------------------------
// Embedding gather
// ---------------------------------------------------------------------------
__global__ void embed_kernel(const int* __restrict__ tok,
                             const float* __restrict__ emb,
                             float* __restrict__ x) {
    int row = blockIdx.x;
    int t = tok[row];
    const float4* src = (const float4*)(emb + (size_t)t * DIM);
    float4* dst = (float4*)(x + (size_t)row * DIM);
    for (int i = threadIdx.x; i < DIM / 4; i += blockDim.x) dst[i] = src[i];
}

// ---------------------------------------------------------------------------
// LayerNorm: optional fp32 out and/or bf16 hi/lo out.
// ---------------------------------------------------------------------------
__global__ void __launch_bounds__(256) ln_kernel(const float* __restrict__ src, int lds,
                                                 const float* __restrict__ gamma,
                                                 float* __restrict__ dstF,
                                                 __nv_bfloat16* __restrict__ hi,
                                                 __nv_bfloat16* __restrict__ lo,
                                                 int ldd, int D) {
    int row = blockIdx.x;
    const float* x = src + (size_t)row * lds;
    float s = 0.f, s2 = 0.f;
    for (int i = threadIdx.x; i < D; i += 256) {
        float v = x[i];
        s += v; s2 += v * v;
    }
    __shared__ float sh[64];
    #pragma unroll
    for (int o = 16; o; o >>= 1) {
        s  += __shfl_xor_sync(0xFFFFFFFFu, s,  o);
        s2 += __shfl_xor_sync(0xFFFFFFFFu, s2, o);
    }
    int warp = threadIdx.x >> 5, lane = threadIdx.x & 31;
    if (lane == 0) { sh[warp] = s; sh[32 + warp] = s2; }
    __syncthreads();
    if (warp == 0) {
        s  = (lane < 8) ? sh[lane]      : 0.f;
        s2 = (lane < 8) ? sh[32 + lane] : 0.f;
        #pragma unroll
        for (int o = 4; o; o >>= 1) {
            s  += __shfl_xor_sync(0xFFFFFFFFu, s,  o);
            s2 += __shfl_xor_sync(0xFFFFFFFFu, s2, o);
        }
        if (lane == 0) {
            float mean = s / D;
            float var  = s2 / D - mean * mean;
            sh[0] = mean;
            sh[1] = rsqrtf(var + 1e-5f);
        }
    }
    __syncthreads();
    float mean = sh[0], rstd = sh[1];
    for (int i = threadIdx.x * 2; i < D; i += 512) {
        float v0 = (x[i]     - mean) * rstd * gamma[i];
        float v1 = (x[i + 1] - mean) * rstd * gamma[i + 1];
        size_t o = (size_t)row * ldd + i;
        if (dstF) { dstF[o] = v0; dstF[o + 1] = v1; }
        if (hi) {
            float h0 = bf16r(v0), h1 = bf16r(v1);
            *(uint32_t*)(hi + o) = pack_bf2(h0, h1);
            *(uint32_t*)(lo + o) = pack_bf2(v0 - h0, v1 - h1);
        }
    }
}

// ---------------------------------------------------------------------------
// Split A (fp32 -> bf16 hi/lo) with tril mask — only used for g_sw.
// ---------------------------------------------------------------------------
__global__ void __launch_bounds__(256) splitA_k(const float* __restrict__ A,
                                                __nv_bfloat16* __restrict__ hi,
                                                __nv_bfloat16* __restrict__ lo,
                                                int MK, int K, int tril) {
    int i4 = (blockIdx.x * 256 + threadIdx.x) * 4;
    if (i4 >= MK) return;
    float4 v = *(const float4*)(A + i4);
    float vv[4] = {v.x, v.y, v.z, v.w};
    if (tril) {
        int m = i4 / K, k = i4 - m * K;
        #pragma unroll
        for (int e = 0; e < 4; e++)
            if (k + e > m) vv[e] = 0.f;
    }
    float hf[4];
    #pragma unroll
    for (int e = 0; e < 4; e++) hf[e] = bf16r(vv[e]);
    uint2 ho, lo2;
    ho.x  = pack_bf2(hf[0], hf[1]); ho.y  = pack_bf2(hf[2], hf[3]);
    lo2.x = pack_bf2(vv[0] - hf[0], vv[1] - hf[1]);
    lo2.y = pack_bf2(vv[2] - hf[2], vv[3] - hf[3]);
    *(uint2*)(hi + i4) = ho;
    *(uint2*)(lo + i4) = lo2;
}

// ---------------------------------------------------------------------------
// Transpose + split B: B[K][N] fp32 -> Bt hi/lo bf16 [N][K]
// ---------------------------------------------------------------------------
__global__ void __launch_bounds__(256) tspB_k(const float* __restrict__ B,
                                              __nv_bfloat16* __restrict__ hi,
                                              __nv_bfloat16* __restrict__ lo,
                                              int K, int N) {
    __shared__ float sh[32][33];
    int nt = blockIdx.x * 32, kt = blockIdx.y * 32;
    int tx = threadIdx.x & 31, ty = threadIdx.x >> 5;
    #pragma unroll
    for (int j = 0; j < 32; j += 8)
        sh[ty + j][tx] = B[(size_t)(kt + ty + j) * N + nt + tx];
    __syncthreads();
    #pragma unroll
    for (int j = 0; j < 32; j += 8) {
        float v = sh[tx][ty + j];
        float h = bf16r(v);
        size_t o = (size_t)(nt + ty + j) * K + kt + tx;
        hi[o] = __float2bfloat16(h);
        lo[o] = __float2bfloat16(v - h);
    }
}

// ---------------------------------------------------------------------------
// Split-bf16 3-term tensor-core GEMM, templated on BM (64 or 128 M-tile).
// ---------------------------------------------------------------------------
enum { F_BIAS = 1, F_GELU = 2, F_RES = 4, F_MULX = 16, F_ROWB = 32, F_SPLIT = 64 };

#define BTILE_BYTES 10240   // 128 rows x 80B

template <int FLAGS, int BM>
__global__ void __launch_bounds__(256, (BM == 64) ? 3 : 2) gemm_bf3(
    const __nv_bfloat16* __restrict__ Ahi, const __nv_bfloat16* __restrict__ Alo,
    const __nv_bfloat16* __restrict__ Bhi, const __nv_bfloat16* __restrict__ Blo,
    const float* __restrict__ bias, const float* __restrict__ rbias,
    const float* __restrict__ Xm, int ldx,
    const float* __restrict__ resid,
    float* __restrict__ C,
    __nv_bfloat16* __restrict__ Chi, __nv_bfloat16* __restrict__ Clo,
    int M, int N, int K) {

    constexpr int ATILE = BM * 80;
    constexpr int STAGE = 2 * ATILE + 2 * BTILE_BYTES;
    constexpr int UP    = (BM == 128) ? 4 : 2;

    extern __shared__ char dsm[];
    const uint32_t smem_base = s2u(dsm);

    const int tid  = threadIdx.x;
    const int wid  = tid >> 5;
    const int lane = tid & 31;
    const int wm   = (BM == 128) ? (wid >> 1) : (wid & 1);
    const int wn   = (BM == 128) ? (wid & 1)  : (wid >> 1);
    const int bm = blockIdx.y * BM, bn = blockIdx.x * 128;

    float acc[2][2 * UP][4];
    #pragma unroll
    for (int i = 0; i < 2; i++)
        #pragma unroll
        for (int j = 0; j < 2 * UP; j++)
            #pragma unroll
            for (int e = 0; e < 4; e++) acc[i][j][e] = 0.f;

    const __nv_bfloat16* bases[4] = {
        Ahi + (size_t)bm * K, Alo + (size_t)bm * K,
        Bhi + (size_t)bn * K, Blo + (size_t)bn * K };

    const int mi  = lane >> 3;
    const int lr8 = lane & 7;
    const int a_off = ((mi & 1) * 8 + lr8) * 80 + (mi >> 1) * 16;
    const int b_off = ((mi >> 1) * 8 + lr8) * 80 + (mi & 1) * 16;

    const int nK = K >> 5;

    #define LOAD_STAGE(s, kt) do {                                             \
        uint32_t sb_ = smem_base + (s) * STAGE;                                \
        int kc_ = (kt) << 5;                                                   \
        _Pragma("unroll")                                                      \
        for (int t = 0; t < (2 * BM * 4) / 256; t++) {                         \
            int w = t * 256 + tid;                                             \
            int tile = w / (BM * 4);                                           \
            int row = (w % (BM * 4)) >> 2, ch = w & 3;                         \
            const char* src = (const char*)(bases[tile] + (size_t)row * K + kc_ + ch * 8); \
            uint32_t dst = sb_ + tile * ATILE + row * 80 + ch * 16;            \
            CP_ASYNC16(dst, src);                                              \
        }                                                                      \
        _Pragma("unroll")                                                      \
        for (int t = 0; t < 4; t++) {                                          \
            int w = t * 256 + tid;                                             \
            int bt = w >> 9;                                                   \
            int row = (w & 511) >> 2, ch = w & 3;                              \
            const char* src = (const char*)(bases[2 + bt] + (size_t)row * K + kc_ + ch * 8); \
            uint32_t dst = sb_ + 2 * ATILE + bt * BTILE_BYTES + row * 80 + ch * 16; \
            CP_ASYNC16(dst, src);                                              \
        }                                                                      \
        CP_COMMIT();                                                           \
    } while (0)

    LOAD_STAGE(0, 0);

    for (int kt = 0; kt < nK; kt++) {
        int s = kt & 1;
        if (kt + 1 < nK) {
            LOAD_STAGE(s ^ 1, kt + 1);
            CP_WAIT1();
        } else {
            CP_WAIT0();
        }
        __syncthreads();

        uint32_t TAh = smem_base + s * STAGE;
        uint32_t TAl = TAh + ATILE;
        uint32_t TBh = TAh + 2 * ATILE;
        uint32_t TBl = TBh + BTILE_BYTES;

        #pragma unroll
        for (int ks = 0; ks < 2; ks++) {
            uint32_t ah[2][4], al_[2][4];
            #pragma unroll
            for (int mt = 0; mt < 2; mt++) {
                int rb = (wm * 32 + mt * 16) * 80 + ks * 32;
                LDSM4(ah[mt],  TAh + rb + a_off);
                LDSM4(al_[mt], TAl + rb + a_off);
            }
            uint32_t bh[UP][4], bl[UP][4];
            #pragma unroll
            for (int up = 0; up < UP; up++) {
                int rb = (wn * UP * 16 + up * 16) * 80 + ks * 32;
                LDSM4(bh[up], TBh + rb + b_off);
                LDSM4(bl[up], TBl + rb + b_off);
            }
            #pragma unroll
            for (int term = 0; term < 3; term++) {
                #pragma unroll
                for (int mt = 0; mt < 2; mt++) {
                    const uint32_t* A_ = (term == 2) ? al_[mt] : ah[mt];
                    #pragma unroll
                    for (int up = 0; up < UP; up++) {
                        const uint32_t* B_ = (term == 1) ? bl[up] : bh[up];
                        mma_bf16(acc[mt][2 * up],     A_, &B_[0]);
                        mma_bf16(acc[mt][2 * up + 1], A_, &B_[2]);
                    }
                }
            }
        }
        __syncthreads();
    }

    const int r0 = bm + wm * 32 + (lane >> 2);
    const int cb = bn + wn * (UP * 16) + (lane & 3) * 2;
    #pragma unroll
    for (int mt = 0; mt < 2; mt++) {
        #pragma unroll
        for (int nt = 0; nt < 2 * UP; nt++) {
            float* a4 = acc[mt][nt];
            int gm = r0 + mt * 16;
            int gn = cb + nt * 8;
            float vv[4];
            #pragma unroll
            for (int e = 0; e < 4; e++) {
                int rr = gm + (e >> 1) * 8;
                int cc = gn + (e & 1);
                float v = a4[e];
                if (FLAGS & F_BIAS) v += bias[cc];
                if (FLAGS & F_ROWB) v += rbias[rr];
                if (FLAGS & F_GELU) v = gelu_f(v);
                if (FLAGS & F_MULX) v *= Xm[(size_t)rr * ldx + cc];
                if (FLAGS & F_RES)  v += resid[(size_t)rr * N + cc];
                vv[e] = v;
            }
            size_t o0 = (size_t)gm * N + gn;
            size_t o1 = (size_t)(gm + 8) * N + gn;
            *(float2*)(C + o0) = make_float2(vv[0], vv[1]);
            *(float2*)(C + o1) = make_float2(vv[2], vv[3]);
            if (FLAGS & F_SPLIT) {
                float h0 = bf16r(vv[0]), h1 = bf16r(vv[1]);
                float h2 = bf16r(vv[2]), h3 = bf16r(vv[3]);
                *(uint32_t*)(Chi + o0) = pack_bf2(h0, h1);
                *(uint32_t*)(Chi + o1) = pack_bf2(h2, h3);
                *(uint32_t*)(Clo + o0) = pack_bf2(vv[0] - h0, vv[1] - h1);
                *(uint32_t*)(Clo + o1) = pack_bf2(vv[2] - h2, vv[3] - h3);
            }
        }
    }
}

// ---------------------------------------------------------------------------
// Exact fp32 SIMT GEMM for the head (N=32)
// ---------------------------------------------------------------------------
__global__ void __launch_bounds__(256) gemm_head(
    const float* __restrict__ A, const float* __restrict__ B,
    const float* __restrict__ bias, float* __restrict__ C,
    int M, int N, int K) {
    __shared__ float As[16][128];
    __shared__ float Bs[16][32];
    const int tid = threadIdx.x;
    const int bm = blockIdx.y * 128;
    const int r = tid >> 1;
    const int cp = (tid & 1) * 16;
    float acc[16];
    #pragma unroll
    for (int j = 0; j < 16; j++) acc[j] = 0.f;

    const int a_row = tid >> 2, a_col = (tid & 3) << 2;
    const int b_row = tid >> 3, b_col = (tid & 7) << 2;

    for (int kt = 0; kt < K; kt += 16) {
        #pragma unroll
        for (int rr = 0; rr < 2; rr++) {
            int lm = a_row + rr * 64;
            float4 v = *(const float4*)(A + (size_t)(bm + lm) * K + kt + a_col);
            As[a_col + 0][lm] = v.x; As[a_col + 1][lm] = v.y;
            As[a_col + 2][lm] = v.z; As[a_col + 3][lm] = v.w;
        }
        if (b_row < 16) {
            float4 v = *(const float4*)(B + (size_t)(kt + b_row) * N + b_col);
            *(float4*)&Bs[b_row][b_col] = v;
        }
        __syncthreads();
        #pragma unroll
        for (int kk = 0; kk < 16; kk++) {
            float a = As[kk][r];
            #pragma unroll
            for (int j = 0; j < 16; j++) acc[j] += a * Bs[kk][cp + j];
        }
        __syncthreads();
    }
    #pragma unroll
    for (int j = 0; j < 16; j++)
        C[(size_t)(bm + r) * N + cp + j] = acc[j] + bias[cp + j];
}

// ---------------------------------------------------------------------------
// Tensor-core flash attention.
// Block = (64-query tile qt, window w, head h); 128 thr / 4 warps, warp owns
// 16 query rows. Q staged once (x0.125 folded, hi/lo); per 64-key chunk K and
// V staged hi/lo in [row][64] bf16 rows padded to 144 B. S = Q·K^T (3-term),
// online softmax in-fragment (quad shfl row reduce), P hi/lo re-split feeds
// P·V (3-term) with ldmatrix.trans on V[key][dim]. Emits ATT hi/lo directly.
// ---------------------------------------------------------------------------
#define AQH 0
#define AQL 9216
#define AKH 18432
#define AKL 27648
#define AVH 36864
#define AVL 46080
#define ATT_SMEM 55296

__global__ void __launch_bounds__(128, 3) attn_tc(const float* __restrict__ qkv,
                                                  __nv_bfloat16* __restrict__ athi,
                                                  __nv_bfloat16* __restrict__ atlo) {
    extern __shared__ char dsm[];
    const uint32_t sb = s2u(dsm);

    const int h  = blockIdx.z;
    const int w  = blockIdx.y;
    const int qt = blockIdx.x;
    const int tid  = threadIdx.x;
    const int wm   = tid >> 5;
    const int lane = tid & 31;
    const int mi   = lane >> 3;
    const int lr8  = lane & 7;

    // ---- stage Q (once): row tid>>1, dims (tid&1)*32..+31, x0.125, hi/lo ----
    {
        int row = tid >> 1, halfd = tid & 1;
        int tq = w * WSZ + qt * 64 + row;
        const float4* qp = (const float4*)(qkv + (size_t)tq * (3 * INNER) + h * DHEAD + halfd * 32);
        char* dh = dsm + AQH + row * 144 + halfd * 64;
        char* dl = dsm + AQL + row * 144 + halfd * 64;
        #pragma unroll
        for (int f = 0; f < 8; f++) {
            float4 v = qp[f];
            float a0 = v.x * 0.125f, a1 = v.y * 0.125f, a2 = v.z * 0.125f, a3 = v.w * 0.125f;
            float h0 = bf16r(a0), h1 = bf16r(a1), h2 = bf16r(a2), h3 = bf16r(a3);
            uint2 uh, ul;
            uh.x = pack_bf2(h0, h1); uh.y = pack_bf2(h2, h3);
            ul.x = pack_bf2(a0 - h0, a1 - h1); ul.y = pack_bf2(a2 - h2, a3 - h3);
            *(uint2*)(dh + f * 8) = uh;
            *(uint2*)(dl + f * 8) = ul;
        }
    }
    __syncthreads();

    // ---- preload Q fragments (chunk-invariant): 4 k-steps x hi/lo ----
    uint32_t qf_h[4][4], qf_l[4][4];
    {
        uint32_t abase = sb + (wm * 16 + (mi & 1) * 8 + lr8) * 144 + (mi >> 1) * 16;
        #pragma unroll
        for (int ks = 0; ks < 4; ks++) {
            LDSM4(qf_h[ks], abase + AQH + ks * 32);
            LDSM4(qf_l[ks], abase + AQL + ks * 32);
        }
    }

    float Oacc[8][4];
    #pragma unroll
    for (int nt = 0; nt < 8; nt++)
        #pragma unroll
        for (int e = 0; e < 4; e++) Oacc[nt][e] = 0.f;
    float mrow[2] = {-1e30f, -1e30f};
    float lrow[2] = {0.f, 0.f};

    const int i_base = qt * 64 + wm * 16 + (lane >> 2);  // query row (window-rel)
    const int nchunk = qt + 9;

    const uint32_t boffKV = ((mi >> 1) * 8 + lr8) * 144 + (mi & 1) * 16;   // non-trans (K)
    const uint32_t toffV  = ((mi & 1) * 8 + lr8) * 144 + (mi >> 1) * 16;   // trans (V)

    for (int c = 0; c < nchunk; c++) {
        int j0 = c * 64;
        __syncthreads();   // previous chunk fully consumed

        // ---- stage K, V chunk (rows = key 0..63) ----
        {
            int row = tid >> 1, halfd = tid & 1;
            int tk = (w - 1) * WSZ + j0 + row;
            const float4* kp = (const float4*)(qkv + (size_t)tk * (3 * INNER) + INNER + h * DHEAD + halfd * 32);
            const float4* vp = kp + INNER / 4;
            char* dkh = dsm + AKH + row * 144 + halfd * 64;
            char* dkl = dsm + AKL + row * 144 + halfd * 64;
            char* dvh = dsm + AVH + row * 144 + halfd * 64;
            char* dvl = dsm + AVL + row * 144 + halfd * 64;
            #pragma unroll
            for (int f = 0; f < 8; f++) {
                float4 kv = make_float4(0.f, 0.f, 0.f, 0.f);
                float4 vv = make_float4(0.f, 0.f, 0.f, 0.f);
                if (tk >= 0) { kv = kp[f]; vv = vp[f]; }
                float kh0 = bf16r(kv.x), kh1 = bf16r(kv.y), kh2 = bf16r(kv.z), kh3 = bf16r(kv.w);
                float vh0 = bf16r(vv.x), vh1 = bf16r(vv.y), vh2 = bf16r(vv.z), vh3 = bf16r(vv.w);
                uint2 u;
                u.x = pack_bf2(kh0, kh1); u.y = pack_bf2(kh2, kh3);
                *(uint2*)(dkh + f * 8) = u;
                u.x = pack_bf2(kv.x - kh0, kv.y - kh1); u.y = pack_bf2(kv.z - kh2, kv.w - kh3);
                *(uint2*)(dkl + f * 8) = u;
                u.x = pack_bf2(vh0, vh1); u.y = pack_bf2(vh2, vh3);
                *(uint2*)(dvh + f * 8) = u;
                u.x = pack_bf2(vv.x - vh0, vv.y - vh1); u.y = pack_bf2(vv.z - vh2, vv.w - vh3);
                *(uint2*)(dvl + f * 8) = u;
            }
        }
        __syncthreads();

        // ---- S = Q @ K^T : m16 x n64, 3-term ----
        float Sa[8][4];
        #pragma unroll
        for (int nt = 0; nt < 8; nt++)
            #pragma unroll
            for (int e = 0; e < 4; e++) Sa[nt][e] = 0.f;

        #pragma unroll
        for (int ks = 0; ks < 4; ks++) {
            #pragma unroll
            for (int ng = 0; ng < 4; ng++) {
                uint32_t kb = sb + (ng * 16) * 144 + boffKV + ks * 32;
                uint32_t kh4[4], kl4[4];
                LDSM4(kh4, kb + AKH);
                LDSM4(kl4, kb + AKL);
                mma_bf16(Sa[2 * ng],     qf_h[ks], &kh4[0]);
                mma_bf16(Sa[2 * ng],     qf_h[ks], &kl4[0]);
                mma_bf16(Sa[2 * ng],     qf_l[ks], &kh4[0]);
                mma_bf16(Sa[2 * ng + 1], qf_h[ks], &kh4[2]);
                mma_bf16(Sa[2 * ng + 1], qf_h[ks], &kl4[2]);
                mma_bf16(Sa[2 * ng + 1], qf_l[ks], &kh4[2]);
            }
        }

        // ---- mask ----
        #pragma unroll
        for (int nt = 0; nt < 8; nt++)
            #pragma unroll
            for (int e = 0; e < 4; e++) {
                int col = j0 + nt * 8 + (lane & 3) * 2 + (e & 1);
                int ri  = i_base + (e >> 1) * 8;
                if (col > ri + WSZ) Sa[nt][e] = -1e30f;
            }

        // ---- online softmax (per row-half) ----
        #pragma unroll
        for (int e2 = 0; e2 < 2; e2++) {
            float mx = -1e30f;
            #pragma unroll
            for (int nt = 0; nt < 8; nt++) {
                mx = fmaxf(mx, Sa[nt][e2 * 2]);
                mx = fmaxf(mx, Sa[nt][e2 * 2 + 1]);
            }
            mx = fmaxf(mx, __shfl_xor_sync(0xFFFFFFFFu, mx, 1));
            mx = fmaxf(mx, __shfl_xor_sync(0xFFFFFFFFu, mx, 2));
            float mnew = fmaxf(mrow[e2], mx);
            float corr = __expf(mrow[e2] - mnew);
            mrow[e2] = mnew;
            lrow[e2] *= corr;
            #pragma unroll
            for (int nt = 0; nt < 8; nt++) {
                Oacc[nt][e2 * 2]     *= corr;
                Oacc[nt][e2 * 2 + 1] *= corr;
            }
            float psum = 0.f;
            #pragma unroll
            for (int nt = 0; nt < 8; nt++) {
                float p0 = __expf(Sa[nt][e2 * 2]     - mnew);
                float p1 = __expf(Sa[nt][e2 * 2 + 1] - mnew);
                Sa[nt][e2 * 2]     = p0;
                Sa[nt][e2 * 2 + 1] = p1;
                psum += p0 + p1;
            }
            lrow[e2] += psum;
        }

        // ---- O += P @ V : 3-term, V via ldmatrix.trans ----
        #pragma unroll
        for (int kt = 0; kt < 4; kt++) {
            uint32_t ph[4], pl[4];
            #pragma unroll
            for (int half = 0; half < 2; half++) {        // a0/a1 from Sa[2kt], a2/a3 from Sa[2kt+1]
                float s0 = Sa[2 * kt + half][0], s1 = Sa[2 * kt + half][1];
                float s2 = Sa[2 * kt + half][2], s3 = Sa[2 * kt + half][3];
                float h0 = bf16r(s0), h1 = bf16r(s1), h2 = bf16r(s2), h3 = bf16r(s3);
                ph[2 * half]     = pack_bf2(h0, h1);
                ph[2 * half + 1] = pack_bf2(h2, h3);
                pl[2 * half]     = pack_bf2(s0 - h0, s1 - h1);
                pl[2 * half + 1] = pack_bf2(s2 - h2, s3 - h3);
            }
            #pragma unroll
            for (int vt = 0; vt < 4; vt++) {
                uint32_t vb = sb + (kt * 16) * 144 + toffV + vt * 32;
                uint32_t vh4[4], vl4[4];
                LDSM4T(vh4, vb + AVH);
                LDSM4T(vl4, vb + AVL);
                mma_bf16(Oacc[2 * vt],     ph, &vh4[0]);
                mma_bf16(Oacc[2 * vt],     pl, &vh4[0]);
                mma_bf16(Oacc[2 * vt],     ph, &vl4[0]);
                mma_bf16(Oacc[2 * vt + 1], ph, &vh4[2]);
                mma_bf16(Oacc[2 * vt + 1], pl, &vh4[2]);
                mma_bf16(Oacc[2 * vt + 1], ph, &vl4[2]);
            }
        }
    }

    // ---- finalize: quad-reduce l, normalize, emit hi/lo ----
    float inv[2];
    #pragma unroll
    for (int e2 = 0; e2 < 2; e2++) {
        float l = lrow[e2];
        l += __shfl_xor_sync(0xFFFFFFFFu, l, 1);
        l += __shfl_xor_sync(0xFFFFFFFFu, l, 2);
        inv[e2] = 1.f / l;
    }
    const int tok0 = w * WSZ + qt * 64 + wm * 16 + (lane >> 2);
    const int cb   = h * DHEAD + (lane & 3) * 2;
    #pragma unroll
    for (int nt = 0; nt < 8; nt++) {
        #pragma unroll
        for (int e2 = 0; e2 < 2; e2++) {
            int tok = tok0 + e2 * 8;
            float a = Oacc[nt][e2 * 2]     * inv[e2];
            float b = Oacc[nt][e2 * 2 + 1] * inv[e2];
            float ha = bf16r(a), hb = bf16r(b);
            size_t o = (size_t)tok * INNER + cb + nt * 8;
            *(uint32_t*)(athi + o) = pack_bf2(ha, hb);
            *(uint32_t*)(atlo + o) = pack_bf2(a - ha, b - hb);
        }
    }
}

// ---------------------------------------------------------------------------
// Host-side dispatch
// ---------------------------------------------------------------------------
static __nv_bfloat16 *BHI, *BLO;

#define SMEM64  (2 * (2 * 64  * 80 + 2 * BTILE_BYTES))   // 61440
#define SMEM128 (2 * (2 * 128 * 80 + 2 * BTILE_BYTES))   // 81920

static void gemm(int flags, const __nv_bfloat16* Ahi, const __nv_bfloat16* Alo,
                 const float* B, const float* bias, const float* rbias,
                 const float* Xm, int ldx, const float* resid,
                 float* C, __nv_bfloat16* Chi, __nv_bfloat16* Clo,
                 int M, int N, int K) {
    tspB_k<<<dim3(N / 32, K / 32), 256>>>(B, BHI, BLO, K, N);
    if (N <= 1536) {
        dim3 grid(N / 128, M / 64);
        switch (flags) {
            case 0:
                gemm_bf3<0, 64><<<grid, 256, SMEM64>>>(Ahi, Alo, BHI, BLO, bias, rbias, Xm, ldx, resid, C, Chi, Clo, M, N, K); break;
            case F_BIAS | F_RES:
                gemm_bf3<F_BIAS | F_RES, 64><<<grid, 256, SMEM64>>>(Ahi, Alo, BHI, BLO, bias, rbias, Xm, ldx, resid, C, Chi, Clo, M, N, K); break;
        }
    } else {
        dim3 grid(N / 128, M / 128);
        switch (flags) {
            case F_BIAS | F_GELU:
                gemm_bf3<F_BIAS | F_GELU, 128><<<grid, 256, SMEM128>>>(Ahi, Alo, BHI, BLO, bias, rbias, Xm, ldx, resid, C, Chi, Clo, M, N, K); break;
            case F_BIAS | F_GELU | F_SPLIT:
                gemm_bf3<F_BIAS | F_GELU | F_SPLIT, 128><<<grid, 256, SMEM128>>>(Ahi, Alo, BHI, BLO, bias, rbias, Xm, ldx, resid, C, Chi, Clo, M, N, K); break;
            case F_ROWB | F_MULX | F_SPLIT:
                gemm_bf3<F_ROWB | F_MULX | F_SPLIT, 128><<<grid, 256, SMEM128>>>(Ahi, Alo, BHI, BLO, bias, rbias, Xm, ldx, resid, C, Chi, Clo, M, N, K); break;
            case F_BIAS | F_SPLIT:
                gemm_bf3<F_BIAS | F_SPLIT, 128><<<grid, 256, SMEM128>>>(Ahi, Alo, BHI, BLO, bias, rbias, Xm, ldx, resid, C, Chi, Clo, M, N, K); break;
        }
    }
}

extern "C" void kernel_launch(void* const* d_in, const int* in_sizes, int n_in,
                              void* d_out, int out_size) {
    (void)in_sizes; (void)n_in;
    const int*   tokens   = (const int*)  d_in[0];
    const float* embed    = (const float*)d_in[1];
    const float* attn_ln  = (const float*)d_in[2];
    const float* attn_qkv = (const float*)d_in[3];
    const float* attn_ow  = (const float*)d_in[4];
    const float* attn_ob  = (const float*)d_in[5];
    const float* ff_ln    = (const float*)d_in[6];
    const float* ff_w1    = (const float*)d_in[7];
    const float* ff_b1    = (const float*)d_in[8];
    const float* ff_w2    = (const float*)d_in[9];
    const float* ff_b2    = (const float*)d_in[10];
    const float* gl_ln    = (const float*)d_in[11];
    const float* g_win    = (const float*)d_in[12];
    const float* g_bin    = (const float*)d_in[13];
    const float* g_sln    = (const float*)d_in[14];
    const float* g_sw     = (const float*)d_in[15];
    const float* g_sb     = (const float*)d_in[16];
    const float* g_sow    = (const float*)d_in[17];
    const float* g_sob    = (const float*)d_in[18];
    const float* g_pow    = (const float*)d_in[19];
    const float* g_pob    = (const float*)d_in[20];
    const float* fin_ln   = (const float*)d_in[21];
    const float* head_w   = (const float*)d_in[22];
    const float* head_b   = (const float*)d_in[23];
    float* out = (float*)d_out;
    (void)out_size;

    float *X, *XN, *QKV, *H, *GT, *TP;
    __nv_bfloat16 *XNHI, *XNLO, *HHI, *HLO, *ATHI, *ATLO, *TPHI, *TPLO,
                  *G2HI, *G2LO, *SWHI, *SWLO;
    cudaGetSymbolAddress((void**)&X,    g_x);
    cudaGetSymbolAddress((void**)&XN,   g_xn);
    cudaGetSymbolAddress((void**)&QKV,  g_qkv);
    cudaGetSymbolAddress((void**)&H,    g_h);
    cudaGetSymbolAddress((void**)&GT,   g_gt);
    cudaGetSymbolAddress((void**)&TP,   g_tp);
    cudaGetSymbolAddress((void**)&XNHI, g_xnhi);
    cudaGetSymbolAddress((void**)&XNLO, g_xnlo);
    cudaGetSymbolAddress((void**)&HHI,  g_hhi);
    cudaGetSymbolAddress((void**)&HLO,  g_hlo);
    cudaGetSymbolAddress((void**)&ATHI, g_athi);
    cudaGetSymbolAddress((void**)&ATLO, g_atlo);
    cudaGetSymbolAddress((void**)&TPHI, g_tphi);
    cudaGetSymbolAddress((void**)&TPLO, g_tplo);
    cudaGetSymbolAddress((void**)&G2HI, g_g2hi);
    cudaGetSymbolAddress((void**)&G2LO, g_g2lo);
    cudaGetSymbolAddress((void**)&SWHI, g_swhi);
    cudaGetSymbolAddress((void**)&SWLO, g_swlo);
    cudaGetSymbolAddress((void**)&BHI,  g_bhi);
    cudaGetSymbolAddress((void**)&BLO,  g_blo);

    cudaFuncSetAttribute((const void*)gemm_bf3<0, 64>, cudaFuncAttributeMaxDynamicSharedMemorySize, SMEM64);
    cudaFuncSetAttribute((const void*)gemm_bf3<F_BIAS | F_RES, 64>, cudaFuncAttributeMaxDynamicSharedMemorySize, SMEM64);
    cudaFuncSetAttribute((const void*)gemm_bf3<F_BIAS | F_GELU, 128>, cudaFuncAttributeMaxDynamicSharedMemorySize, SMEM128);
    cudaFuncSetAttribute((const void*)gemm_bf3<F_BIAS | F_GELU | F_SPLIT, 128>, cudaFuncAttributeMaxDynamicSharedMemorySize, SMEM128);
    cudaFuncSetAttribute((const void*)gemm_bf3<F_ROWB | F_MULX | F_SPLIT, 128>, cudaFuncAttributeMaxDynamicSharedMemorySize, SMEM128);
    cudaFuncSetAttribute((const void*)gemm_bf3<F_BIAS | F_SPLIT, 128>, cudaFuncAttributeMaxDynamicSharedMemorySize, SMEM128);
    cudaFuncSetAttribute((const void*)attn_tc, cudaFuncAttributeMaxDynamicSharedMemorySize, ATT_SMEM);

    embed_kernel<<<N_TOK, 256>>>(tokens, embed, X);

    for (int l = 0; l < DEPTH; l++) {
        const float* al = attn_ln  + (size_t)l * DIM;
        const float* aq = attn_qkv + (size_t)l * DIM * 3 * INNER;
        const float* aw = attn_ow  + (size_t)l * INNER * DIM;
        const float* ab = attn_ob  + (size_t)l * DIM;
        const float* fl = ff_ln    + (size_t)l * DIM;
        const float* f1 = ff_w1    + (size_t)l * DIM * DFF;
        const float* b1 = ff_b1    + (size_t)l * DFF;
        const float* f2 = ff_w2    + (size_t)l * DFF * DIM;
        const float* b2 = ff_b2    + (size_t)l * DIM;

        ln_kernel<<<N_TOK, 256>>>(X, DIM, al, nullptr, XNHI, XNLO, DIM, DIM);
        gemm(0, XNHI, XNLO, aq, nullptr, nullptr, nullptr, 0, nullptr,
             QKV, nullptr, nullptr, N_TOK, 3 * INNER, DIM);
        attn_tc<<<dim3(8, 4, NHEAD), 128, ATT_SMEM>>>(QKV, ATHI, ATLO);
        gemm(F_BIAS | F_RES, ATHI, ATLO, aw, ab, nullptr, nullptr, 0, X,
             X, nullptr, nullptr, N_TOK, DIM, INNER);

        ln_kernel<<<N_TOK, 256>>>(X, DIM, fl, nullptr, XNHI, XNLO, DIM, DIM);
        gemm(F_BIAS | F_GELU | F_SPLIT, XNHI, XNLO, f1, b1, nullptr, nullptr, 0, nullptr,
             H, HHI, HLO, N_TOK, DFF, DIM);
        gemm(F_BIAS | F_RES, HHI, HLO, f2, b2, nullptr, nullptr, 0, X,
             X, nullptr, nullptr, N_TOK, DIM, DFF);
    }

    for (int g = 0; g < GDEPTH; g++) {
        const float* gl  = gl_ln + (size_t)g * DIM;
        const float* wi  = g_win + (size_t)g * DIM * DFF;
        const float* bi  = g_bin + (size_t)g * DFF;
        const float* sl  = g_sln + (size_t)g * HALF;
        const float* sw  = g_sw  + (size_t)g * N_TOK * N_TOK;
        const float* sb  = g_sb  + (size_t)g * N_TOK;
        const float* so  = g_sow + (size_t)g * HALF * HALF;
        const float* sob = g_sob + (size_t)g * HALF;
        const float* po  = g_pow + (size_t)g * HALF * DIM;
        const float* pob = g_pob + (size_t)g * DIM;

        ln_kernel<<<N_TOK, 256>>>(X, DIM, gl, nullptr, XNHI, XNLO, DIM, DIM);
        gemm(F_BIAS | F_GELU, XNHI, XNLO, wi, bi, nullptr, nullptr, 0, nullptr,
             H, nullptr, nullptr, N_TOK, DFF, DIM);
        ln_kernel<<<N_TOK, 256>>>(H + HALF, DFF, sl, GT, nullptr, nullptr, HALF, HALF);
        splitA_k<<<(N_TOK * N_TOK / 4 + 255) / 256, 256>>>(sw, SWHI, SWLO,
                                                           N_TOK * N_TOK, N_TOK, 1);
        gemm(F_ROWB | F_MULX | F_SPLIT, SWHI, SWLO, GT, nullptr, sb, H, DFF, nullptr,
             TP, TPHI, TPLO, N_TOK, HALF, N_TOK);
        gemm(F_BIAS | F_SPLIT, TPHI, TPLO, so, sob, nullptr, nullptr, 0, nullptr,
             GT, G2HI, G2LO, N_TOK, HALF, HALF);
        gemm(F_BIAS | F_RES, G2HI, G2LO, po, pob, nullptr, nullptr, 0, X,
             X, nullptr, nullptr, N_TOK, DIM, HALF);
    }

    ln_kernel<<<N_TOK, 256>>>(X, DIM, fin_ln, XN, nullptr, nullptr, DIM, DIM);
    gemm_head<<<dim3(1, N_TOK / 128), 256>>>(XN, head_w, head_b, out, N_TOK, VOCAB, DIM);
}

// round 15
// speedup vs baseline: 1.1788x; 1.0086x over previous
#include <cuda_runtime.h>
#include <cuda_bf16.h>
#include <cstdint>

// ---------------------------------------------------------------------------
// Problem constants
// ---------------------------------------------------------------------------
#define N_TOK 2048
#define DIM   1024
#define DFF   4096
#define HALF  2048
#define INNER 512
#define DEPTH 6
#define GDEPTH 2
#define VOCAB 32
#define WSZ   512
#define NHEAD 8
#define DHEAD 64

// ---------------------------------------------------------------------------
// Scratch (device globals — no allocation allowed)
// ---------------------------------------------------------------------------
__device__ float g_x  [N_TOK * DIM];
__device__ float g_xn [N_TOK * DIM];
__device__ float g_qkv[N_TOK * 3 * INNER];
__device__ float g_h  [N_TOK * DFF];
__device__ float g_gt [N_TOK * HALF];
__device__ float g_tp [N_TOK * HALF];
// bf16 split buffers
__device__ __nv_bfloat16 g_xnhi[N_TOK * DIM],   g_xnlo[N_TOK * DIM];
__device__ __nv_bfloat16 g_hhi [N_TOK * DFF],   g_hlo [N_TOK * DFF];
__device__ __nv_bfloat16 g_athi[N_TOK * INNER], g_atlo[N_TOK * INNER];
__device__ __nv_bfloat16 g_tphi[N_TOK * HALF],  g_tplo[N_TOK * HALF];
__device__ __nv_bfloat16 g_g2hi[N_TOK * HALF],  g_g2lo[N_TOK * HALF];
__device__ __nv_bfloat16 g_swhi[N_TOK * N_TOK], g_swlo[N_TOK * N_TOK];
__device__ __nv_bfloat16 g_bhi [4 * 1024 * 1024], g_blo[4 * 1024 * 1024];

// ---------------------------------------------------------------------------
// Helpers
// ---------------------------------------------------------------------------
__device__ __forceinline__ float gelu_f(float x) {
    const float c = 0.7978845608028654f;
    float t = tanhf(c * (x + 0.044715f * x * x * x));
    return 0.5f * x * (1.0f + t);
}

__device__ __forceinline__ uint32_t s2u(const void* p) {
    uint32_t a;
    asm("{ .reg .u64 t; cvta.to.shared.u64 t, %1; cvt.u32.u64 %0, t; }"
        : "=r"(a) : "l"(p));
    return a;
}

#define CP_ASYNC16(dst, src) \
    asm volatile("cp.async.cg.shared.global [%0], [%1], 16;" :: "r"(dst), "l"(src))
#define CP_COMMIT() asm volatile("cp.async.commit_group;" ::: "memory")
#define CP_WAIT0()  asm volatile("cp.async.wait_group 0;" ::: "memory")

#define LDSM4(r, addr) \
    asm volatile("ldmatrix.sync.aligned.m8n8.x4.shared.b16 {%0,%1,%2,%3}, [%4];" \
                 : "=r"((r)[0]), "=r"((r)[1]), "=r"((r)[2]), "=r"((r)[3]) : "r"(addr))

#define LDSM4T(r, addr) \
    asm volatile("ldmatrix.sync.aligned.m8n8.x4.trans.shared.b16 {%0,%1,%2,%3}, [%4];" \
                 : "=r"((r)[0]), "=r"((r)[1]), "=r"((r)[2]), "=r"((r)[3]) : "r"(addr))

__device__ __forceinline__ void mma_bf16(float* c, const uint32_t* a, const uint32_t* b) {
    asm volatile(
        "mma.sync.aligned.m16n8k16.row.col.f32.bf16.bf16.f32 "
        "{%0,%1,%2,%3}, {%4,%5,%6,%7}, {%8,%9}, {%0,%1,%2,%3};"
        : "+f"(c[0]), "+f"(c[1]), "+f"(c[2]), "+f"(c[3])
        : "r"(a[0]), "r"(a[1]), "r"(a[2]), "r"(a[3]), "r"(b[0]), "r"(b[1]));
}

__device__ __forceinline__ uint32_t pack_bf2(float a, float b) {
    __nv_bfloat162 h = __floats2bfloat162_rn(a, b);
    return *(uint32_t*)&h;
}
__device__ __forceinline__ float bf16r(float v) {
    return __bfloat162float(__float2bfloat16(v));
}

// ---------------------------------------------------------------------------
// Embedding gather
// ---------------------------------------------------------------------------
__global__ void embed_kernel(const int* __restrict__ tok,
                             const float* __restrict__ emb,
                             float* __restrict__ x) {
    int row = blockIdx.x;
    int t = tok[row];
    const float4* src = (const float4*)(emb + (size_t)t * DIM);
    float4* dst = (float4*)(x + (size_t)row * DIM);
    for (int i = threadIdx.x; i < DIM / 4; i += blockDim.x) dst[i] = src[i];
}

// ---------------------------------------------------------------------------
// LayerNorm: optional fp32 out and/or bf16 hi/lo out.
// ---------------------------------------------------------------------------
__global__ void __launch_bounds__(256) ln_kernel(const float* __restrict__ src, int lds,
                                                 const float* __restrict__ gamma,
                                                 float* __restrict__ dstF,
                                                 __nv_bfloat16* __restrict__ hi,
                                                 __nv_bfloat16* __restrict__ lo,
                                                 int ldd, int D) {
    int row = blockIdx.x;
    const float* x = src + (size_t)row * lds;
    float s = 0.f, s2 = 0.f;
    for (int i = threadIdx.x; i < D; i += 256) {
        float v = x[i];
        s += v; s2 += v * v;
    }
    __shared__ float sh[64];
    #pragma unroll
    for (int o = 16; o; o >>= 1) {
        s  += __shfl_xor_sync(0xFFFFFFFFu, s,  o);
        s2 += __shfl_xor_sync(0xFFFFFFFFu, s2, o);
    }
    int warp = threadIdx.x >> 5, lane = threadIdx.x & 31;
    if (lane == 0) { sh[warp] = s; sh[32 + warp] = s2; }
    __syncthreads();
    if (warp == 0) {
        s  = (lane < 8) ? sh[lane]      : 0.f;
        s2 = (lane < 8) ? sh[32 + lane] : 0.f;
        #pragma unroll
        for (int o = 4; o; o >>= 1) {
            s  += __shfl_xor_sync(0xFFFFFFFFu, s,  o);
            s2 += __shfl_xor_sync(0xFFFFFFFFu, s2, o);
        }
        if (lane == 0) {
            float mean = s / D;
            float var  = s2 / D - mean * mean;
            sh[0] = mean;
            sh[1] = rsqrtf(var + 1e-5f);
        }
    }
    __syncthreads();
    float mean = sh[0], rstd = sh[1];
    for (int i = threadIdx.x * 2; i < D; i += 512) {
        float v0 = (x[i]     - mean) * rstd * gamma[i];
        float v1 = (x[i + 1] - mean) * rstd * gamma[i + 1];
        size_t o = (size_t)row * ldd + i;
        if (dstF) { dstF[o] = v0; dstF[o + 1] = v1; }
        if (hi) {
            float h0 = bf16r(v0), h1 = bf16r(v1);
            *(uint32_t*)(hi + o) = pack_bf2(h0, h1);
            *(uint32_t*)(lo + o) = pack_bf2(v0 - h0, v1 - h1);
        }
    }
}

// ---------------------------------------------------------------------------
// Split A (fp32 -> bf16 hi/lo) with tril mask — only used for g_sw.
// ---------------------------------------------------------------------------
__global__ void __launch_bounds__(256) splitA_k(const float* __restrict__ A,
                                                __nv_bfloat16* __restrict__ hi,
                                                __nv_bfloat16* __restrict__ lo,
                                                int MK, int K, int tril) {
    int i4 = (blockIdx.x * 256 + threadIdx.x) * 4;
    if (i4 >= MK) return;
    float4 v = *(const float4*)(A + i4);
    float vv[4] = {v.x, v.y, v.z, v.w};
    if (tril) {
        int m = i4 / K, k = i4 - m * K;
        #pragma unroll
        for (int e = 0; e < 4; e++)
            if (k + e > m) vv[e] = 0.f;
    }
    float hf[4];
    #pragma unroll
    for (int e = 0; e < 4; e++) hf[e] = bf16r(vv[e]);
    uint2 ho, lo2;
    ho.x  = pack_bf2(hf[0], hf[1]); ho.y  = pack_bf2(hf[2], hf[3]);
    lo2.x = pack_bf2(vv[0] - hf[0], vv[1] - hf[1]);
    lo2.y = pack_bf2(vv[2] - hf[2], vv[3] - hf[3]);
    *(uint2*)(hi + i4) = ho;
    *(uint2*)(lo + i4) = lo2;
}

// ---------------------------------------------------------------------------
// Transpose + split B: B[K][N] fp32 -> Bt hi/lo bf16 [N][K]
// ---------------------------------------------------------------------------
__global__ void __launch_bounds__(256) tspB_k(const float* __restrict__ B,
                                              __nv_bfloat16* __restrict__ hi,
                                              __nv_bfloat16* __restrict__ lo,
                                              int K, int N) {
    __shared__ float sh[32][33];
    int nt = blockIdx.x * 32, kt = blockIdx.y * 32;
    int tx = threadIdx.x & 31, ty = threadIdx.x >> 5;
    #pragma unroll
    for (int j = 0; j < 32; j += 8)
        sh[ty + j][tx] = B[(size_t)(kt + ty + j) * N + nt + tx];
    __syncthreads();
    #pragma unroll
    for (int j = 0; j < 32; j += 8) {
        float v = sh[tx][ty + j];
        float h = bf16r(v);
        size_t o = (size_t)(nt + ty + j) * K + kt + tx;
        hi[o] = __float2bfloat16(h);
        lo[o] = __float2bfloat16(v - h);
    }
}

// ---------------------------------------------------------------------------
// Split-bf16 3-term tensor-core GEMM, templated on BM (64 or 128 M-tile).
// Single-sync mainloop: CP_WAIT0 -> sync -> issue next load -> compute.
// F_NOC: skip dead fp32 C store (hi/lo split outputs only).
// ---------------------------------------------------------------------------
enum { F_BIAS = 1, F_GELU = 2, F_RES = 4, F_MULX = 16, F_ROWB = 32, F_SPLIT = 64,
       F_NOC = 128 };

#define BTILE_BYTES 10240   // 128 rows x 80B

template <int FLAGS, int BM>
__global__ void __launch_bounds__(256, (BM == 64) ? 3 : 2) gemm_bf3(
    const __nv_bfloat16* __restrict__ Ahi, const __nv_bfloat16* __restrict__ Alo,
    const __nv_bfloat16* __restrict__ Bhi, const __nv_bfloat16* __restrict__ Blo,
    const float* __restrict__ bias, const float* __restrict__ rbias,
    const float* __restrict__ Xm, int ldx,
    const float* __restrict__ resid,
    float* __restrict__ C,
    __nv_bfloat16* __restrict__ Chi, __nv_bfloat16* __restrict__ Clo,
    int M, int N, int K) {

    constexpr int ATILE = BM * 80;
    constexpr int STAGE = 2 * ATILE + 2 * BTILE_BYTES;
    constexpr int UP    = (BM == 128) ? 4 : 2;

    extern __shared__ char dsm[];
    const uint32_t smem_base = s2u(dsm);

    const int tid  = threadIdx.x;
    const int wid  = tid >> 5;
    const int lane = tid & 31;
    const int wm   = (BM == 128) ? (wid >> 1) : (wid & 1);
    const int wn   = (BM == 128) ? (wid & 1)  : (wid >> 1);
    const int bm = blockIdx.y * BM, bn = blockIdx.x * 128;

    float acc[2][2 * UP][4];
    #pragma unroll
    for (int i = 0; i < 2; i++)
        #pragma unroll
        for (int j = 0; j < 2 * UP; j++)
            #pragma unroll
            for (int e = 0; e < 4; e++) acc[i][j][e] = 0.f;

    const __nv_bfloat16* bases[4] = {
        Ahi + (size_t)bm * K, Alo + (size_t)bm * K,
        Bhi + (size_t)bn * K, Blo + (size_t)bn * K };

    const int mi  = lane >> 3;
    const int lr8 = lane & 7;
    const int a_off = ((mi & 1) * 8 + lr8) * 80 + (mi >> 1) * 16;
    const int b_off = ((mi >> 1) * 8 + lr8) * 80 + (mi & 1) * 16;

    const int nK = K >> 5;

    #define LOAD_STAGE(s, kt) do {                                             \
        uint32_t sb_ = smem_base + (s) * STAGE;                                \
        int kc_ = (kt) << 5;                                                   \
        _Pragma("unroll")                                                      \
        for (int t = 0; t < (2 * BM * 4) / 256; t++) {                         \
            int w = t * 256 + tid;                                             \
            int tile = w / (BM * 4);                                           \
            int row = (w % (BM * 4)) >> 2, ch = w & 3;                         \
            const char* src = (const char*)(bases[tile] + (size_t)row * K + kc_ + ch * 8); \
            uint32_t dst = sb_ + tile * ATILE + row * 80 + ch * 16;            \
            CP_ASYNC16(dst, src);                                              \
        }                                                                      \
        _Pragma("unroll")                                                      \
        for (int t = 0; t < 4; t++) {                                          \
            int w = t * 256 + tid;                                             \
            int bt = w >> 9;                                                   \
            int row = (w & 511) >> 2, ch = w & 3;                              \
            const char* src = (const char*)(bases[2 + bt] + (size_t)row * K + kc_ + ch * 8); \
            uint32_t dst = sb_ + 2 * ATILE + bt * BTILE_BYTES + row * 80 + ch * 16; \
            CP_ASYNC16(dst, src);                                              \
        }                                                                      \
        CP_COMMIT();                                                           \
    } while (0)

    LOAD_STAGE(0, 0);

    for (int kt = 0; kt < nK; kt++) {
        int s = kt & 1;
        CP_WAIT0();          // this thread's groups done (stage s data landed)
        __syncthreads();     // all threads' stage-s data visible; prior compute done
        if (kt + 1 < nK) LOAD_STAGE(s ^ 1, kt + 1);   // overlaps with compute below

        uint32_t TAh = smem_base + s * STAGE;
        uint32_t TAl = TAh + ATILE;
        uint32_t TBh = TAh + 2 * ATILE;
        uint32_t TBl = TBh + BTILE_BYTES;

        #pragma unroll
        for (int ks = 0; ks < 2; ks++) {
            uint32_t ah[2][4], al_[2][4];
            #pragma unroll
            for (int mt = 0; mt < 2; mt++) {
                int rb = (wm * 32 + mt * 16) * 80 + ks * 32;
                LDSM4(ah[mt],  TAh + rb + a_off);
                LDSM4(al_[mt], TAl + rb + a_off);
            }
            uint32_t bh[UP][4], bl[UP][4];
            #pragma unroll
            for (int up = 0; up < UP; up++) {
                int rb = (wn * UP * 16 + up * 16) * 80 + ks * 32;
                LDSM4(bh[up], TBh + rb + b_off);
                LDSM4(bl[up], TBl + rb + b_off);
            }
            #pragma unroll
            for (int term = 0; term < 3; term++) {
                #pragma unroll
                for (int mt = 0; mt < 2; mt++) {
                    const uint32_t* A_ = (term == 2) ? al_[mt] : ah[mt];
                    #pragma unroll
                    for (int up = 0; up < UP; up++) {
                        const uint32_t* B_ = (term == 1) ? bl[up] : bh[up];
                        mma_bf16(acc[mt][2 * up],     A_, &B_[0]);
                        mma_bf16(acc[mt][2 * up + 1], A_, &B_[2]);
                    }
                }
            }
        }
    }

    const int r0 = bm + wm * 32 + (lane >> 2);
    const int cb = bn + wn * (UP * 16) + (lane & 3) * 2;
    #pragma unroll
    for (int mt = 0; mt < 2; mt++) {
        #pragma unroll
        for (int nt = 0; nt < 2 * UP; nt++) {
            float* a4 = acc[mt][nt];
            int gm = r0 + mt * 16;
            int gn = cb + nt * 8;
            float vv[4];
            #pragma unroll
            for (int e = 0; e < 4; e++) {
                int rr = gm + (e >> 1) * 8;
                int cc = gn + (e & 1);
                float v = a4[e];
                if (FLAGS & F_BIAS) v += bias[cc];
                if (FLAGS & F_ROWB) v += rbias[rr];
                if (FLAGS & F_GELU) v = gelu_f(v);
                if (FLAGS & F_MULX) v *= Xm[(size_t)rr * ldx + cc];
                if (FLAGS & F_RES)  v += resid[(size_t)rr * N + cc];
                vv[e] = v;
            }
            size_t o0 = (size_t)gm * N + gn;
            size_t o1 = (size_t)(gm + 8) * N + gn;
            if (!(FLAGS & F_NOC)) {
                *(float2*)(C + o0) = make_float2(vv[0], vv[1]);
                *(float2*)(C + o1) = make_float2(vv[2], vv[3]);
            }
            if (FLAGS & F_SPLIT) {
                float h0 = bf16r(vv[0]), h1 = bf16r(vv[1]);
                float h2 = bf16r(vv[2]), h3 = bf16r(vv[3]);
                *(uint32_t*)(Chi + o0) = pack_bf2(h0, h1);
                *(uint32_t*)(Chi + o1) = pack_bf2(h2, h3);
                *(uint32_t*)(Clo + o0) = pack_bf2(vv[0] - h0, vv[1] - h1);
                *(uint32_t*)(Clo + o1) = pack_bf2(vv[2] - h2, vv[3] - h3);
            }
        }
    }
}

// ---------------------------------------------------------------------------
// Exact fp32 SIMT GEMM for the head (N=32)
// ---------------------------------------------------------------------------
__global__ void __launch_bounds__(256) gemm_head(
    const float* __restrict__ A, const float* __restrict__ B,
    const float* __restrict__ bias, float* __restrict__ C,
    int M, int N, int K) {
    __shared__ float As[16][128];
    __shared__ float Bs[16][32];
    const int tid = threadIdx.x;
    const int bm = blockIdx.y * 128;
    const int r = tid >> 1;
    const int cp = (tid & 1) * 16;
    float acc[16];
    #pragma unroll
    for (int j = 0; j < 16; j++) acc[j] = 0.f;

    const int a_row = tid >> 2, a_col = (tid & 3) << 2;
    const int b_row = tid >> 3, b_col = (tid & 7) << 2;

    for (int kt = 0; kt < K; kt += 16) {
        #pragma unroll
        for (int rr = 0; rr < 2; rr++) {
            int lm = a_row + rr * 64;
            float4 v = *(const float4*)(A + (size_t)(bm + lm) * K + kt + a_col);
            As[a_col + 0][lm] = v.x; As[a_col + 1][lm] = v.y;
            As[a_col + 2][lm] = v.z; As[a_col + 3][lm] = v.w;
        }
        if (b_row < 16) {
            float4 v = *(const float4*)(B + (size_t)(kt + b_row) * N + b_col);
            *(float4*)&Bs[b_row][b_col] = v;
        }
        __syncthreads();
        #pragma unroll
        for (int kk = 0; kk < 16; kk++) {
            float a = As[kk][r];
            #pragma unroll
            for (int j = 0; j < 16; j++) acc[j] += a * Bs[kk][cp + j];
        }
        __syncthreads();
    }
    #pragma unroll
    for (int j = 0; j < 16; j++)
        C[(size_t)(bm + r) * N + cp + j] = acc[j] + bias[cp + j];
}

// ---------------------------------------------------------------------------
// Tensor-core flash attention (round-14 winner, unchanged).
// ---------------------------------------------------------------------------
#define AQH 0
#define AQL 9216
#define AKH 18432
#define AKL 27648
#define AVH 36864
#define AVL 46080
#define ATT_SMEM 55296

__global__ void __launch_bounds__(128, 3) attn_tc(const float* __restrict__ qkv,
                                                  __nv_bfloat16* __restrict__ athi,
                                                  __nv_bfloat16* __restrict__ atlo) {
    extern __shared__ char dsm[];
    const uint32_t sb = s2u(dsm);

    const int h  = blockIdx.z;
    const int w  = blockIdx.y;
    const int qt = blockIdx.x;
    const int tid  = threadIdx.x;
    const int wm   = tid >> 5;
    const int lane = tid & 31;
    const int mi   = lane >> 3;
    const int lr8  = lane & 7;

    {
        int row = tid >> 1, halfd = tid & 1;
        int tq = w * WSZ + qt * 64 + row;
        const float4* qp = (const float4*)(qkv + (size_t)tq * (3 * INNER) + h * DHEAD + halfd * 32);
        char* dh = dsm + AQH + row * 144 + halfd * 64;
        char* dl = dsm + AQL + row * 144 + halfd * 64;
        #pragma unroll
        for (int f = 0; f < 8; f++) {
            float4 v = qp[f];
            float a0 = v.x * 0.125f, a1 = v.y * 0.125f, a2 = v.z * 0.125f, a3 = v.w * 0.125f;
            float h0 = bf16r(a0), h1 = bf16r(a1), h2 = bf16r(a2), h3 = bf16r(a3);
            uint2 uh, ul;
            uh.x = pack_bf2(h0, h1); uh.y = pack_bf2(h2, h3);
            ul.x = pack_bf2(a0 - h0, a1 - h1); ul.y = pack_bf2(a2 - h2, a3 - h3);
            *(uint2*)(dh + f * 8) = uh;
            *(uint2*)(dl + f * 8) = ul;
        }
    }
    __syncthreads();

    uint32_t qf_h[4][4], qf_l[4][4];
    {
        uint32_t abase = sb + (wm * 16 + (mi & 1) * 8 + lr8) * 144 + (mi >> 1) * 16;
        #pragma unroll
        for (int ks = 0; ks < 4; ks++) {
            LDSM4(qf_h[ks], abase + AQH + ks * 32);
            LDSM4(qf_l[ks], abase + AQL + ks * 32);
        }
    }

    float Oacc[8][4];
    #pragma unroll
    for (int nt = 0; nt < 8; nt++)
        #pragma unroll
        for (int e = 0; e < 4; e++) Oacc[nt][e] = 0.f;
    float mrow[2] = {-1e30f, -1e30f};
    float lrow[2] = {0.f, 0.f};

    const int i_base = qt * 64 + wm * 16 + (lane >> 2);
    const int nchunk = qt + 9;

    const uint32_t boffKV = ((mi >> 1) * 8 + lr8) * 144 + (mi & 1) * 16;
    const uint32_t toffV  = ((mi & 1) * 8 + lr8) * 144 + (mi >> 1) * 16;

    for (int c = 0; c < nchunk; c++) {
        int j0 = c * 64;
        __syncthreads();

        {
            int row = tid >> 1, halfd = tid & 1;
            int tk = (w - 1) * WSZ + j0 + row;
            const float4* kp = (const float4*)(qkv + (size_t)tk * (3 * INNER) + INNER + h * DHEAD + halfd * 32);
            const float4* vp = kp + INNER / 4;
            char* dkh = dsm + AKH + row * 144 + halfd * 64;
            char* dkl = dsm + AKL + row * 144 + halfd * 64;
            char* dvh = dsm + AVH + row * 144 + halfd * 64;
            char* dvl = dsm + AVL + row * 144 + halfd * 64;
            #pragma unroll
            for (int f = 0; f < 8; f++) {
                float4 kv = make_float4(0.f, 0.f, 0.f, 0.f);
                float4 vv = make_float4(0.f, 0.f, 0.f, 0.f);
                if (tk >= 0) { kv = kp[f]; vv = vp[f]; }
                float kh0 = bf16r(kv.x), kh1 = bf16r(kv.y), kh2 = bf16r(kv.z), kh3 = bf16r(kv.w);
                float vh0 = bf16r(vv.x), vh1 = bf16r(vv.y), vh2 = bf16r(vv.z), vh3 = bf16r(vv.w);
                uint2 u;
                u.x = pack_bf2(kh0, kh1); u.y = pack_bf2(kh2, kh3);
                *(uint2*)(dkh + f * 8) = u;
                u.x = pack_bf2(kv.x - kh0, kv.y - kh1); u.y = pack_bf2(kv.z - kh2, kv.w - kh3);
                *(uint2*)(dkl + f * 8) = u;
                u.x = pack_bf2(vh0, vh1); u.y = pack_bf2(vh2, vh3);
                *(uint2*)(dvh + f * 8) = u;
                u.x = pack_bf2(vv.x - vh0, vv.y - vh1); u.y = pack_bf2(vv.z - vh2, vv.w - vh3);
                *(uint2*)(dvl + f * 8) = u;
            }
        }
        __syncthreads();

        float Sa[8][4];
        #pragma unroll
        for (int nt = 0; nt < 8; nt++)
            #pragma unroll
            for (int e = 0; e < 4; e++) Sa[nt][e] = 0.f;

        #pragma unroll
        for (int ks = 0; ks < 4; ks++) {
            #pragma unroll
            for (int ng = 0; ng < 4; ng++) {
                uint32_t kb = sb + (ng * 16) * 144 + boffKV + ks * 32;
                uint32_t kh4[4], kl4[4];
                LDSM4(kh4, kb + AKH);
                LDSM4(kl4, kb + AKL);
                mma_bf16(Sa[2 * ng],     qf_h[ks], &kh4[0]);
                mma_bf16(Sa[2 * ng],     qf_h[ks], &kl4[0]);
                mma_bf16(Sa[2 * ng],     qf_l[ks], &kh4[0]);
                mma_bf16(Sa[2 * ng + 1], qf_h[ks], &kh4[2]);
                mma_bf16(Sa[2 * ng + 1], qf_h[ks], &kl4[2]);
                mma_bf16(Sa[2 * ng + 1], qf_l[ks], &kh4[2]);
            }
        }

        #pragma unroll
        for (int nt = 0; nt < 8; nt++)
            #pragma unroll
            for (int e = 0; e < 4; e++) {
                int col = j0 + nt * 8 + (lane & 3) * 2 + (e & 1);
                int ri  = i_base + (e >> 1) * 8;
                if (col > ri + WSZ) Sa[nt][e] = -1e30f;
            }

        #pragma unroll
        for (int e2 = 0; e2 < 2; e2++) {
            float mx = -1e30f;
            #pragma unroll
            for (int nt = 0; nt < 8; nt++) {
                mx = fmaxf(mx, Sa[nt][e2 * 2]);
                mx = fmaxf(mx, Sa[nt][e2 * 2 + 1]);
            }
            mx = fmaxf(mx, __shfl_xor_sync(0xFFFFFFFFu, mx, 1));
            mx = fmaxf(mx, __shfl_xor_sync(0xFFFFFFFFu, mx, 2));
            float mnew = fmaxf(mrow[e2], mx);
            float corr = __expf(mrow[e2] - mnew);
            mrow[e2] = mnew;
            lrow[e2] *= corr;
            #pragma unroll
            for (int nt = 0; nt < 8; nt++) {
                Oacc[nt][e2 * 2]     *= corr;
                Oacc[nt][e2 * 2 + 1] *= corr;
            }
            float psum = 0.f;
            #pragma unroll
            for (int nt = 0; nt < 8; nt++) {
                float p0 = __expf(Sa[nt][e2 * 2]     - mnew);
                float p1 = __expf(Sa[nt][e2 * 2 + 1] - mnew);
                Sa[nt][e2 * 2]     = p0;
                Sa[nt][e2 * 2 + 1] = p1;
                psum += p0 + p1;
            }
            lrow[e2] += psum;
        }

        #pragma unroll
        for (int kt = 0; kt < 4; kt++) {
            uint32_t ph[4], pl[4];
            #pragma unroll
            for (int half = 0; half < 2; half++) {
                float s0 = Sa[2 * kt + half][0], s1 = Sa[2 * kt + half][1];
                float s2 = Sa[2 * kt + half][2], s3 = Sa[2 * kt + half][3];
                float h0 = bf16r(s0), h1 = bf16r(s1), h2 = bf16r(s2), h3 = bf16r(s3);
                ph[2 * half]     = pack_bf2(h0, h1);
                ph[2 * half + 1] = pack_bf2(h2, h3);
                pl[2 * half]     = pack_bf2(s0 - h0, s1 - h1);
                pl[2 * half + 1] = pack_bf2(s2 - h2, s3 - h3);
            }
            #pragma unroll
            for (int vt = 0; vt < 4; vt++) {
                uint32_t vb = sb + (kt * 16) * 144 + toffV + vt * 32;
                uint32_t vh4[4], vl4[4];
                LDSM4T(vh4, vb + AVH);
                LDSM4T(vl4, vb + AVL);
                mma_bf16(Oacc[2 * vt],     ph, &vh4[0]);
                mma_bf16(Oacc[2 * vt],     pl, &vh4[0]);
                mma_bf16(Oacc[2 * vt],     ph, &vl4[0]);
                mma_bf16(Oacc[2 * vt + 1], ph, &vh4[2]);
                mma_bf16(Oacc[2 * vt + 1], pl, &vh4[2]);
                mma_bf16(Oacc[2 * vt + 1], ph, &vl4[2]);
            }
        }
    }

    float inv[2];
    #pragma unroll
    for (int e2 = 0; e2 < 2; e2++) {
        float l = lrow[e2];
        l += __shfl_xor_sync(0xFFFFFFFFu, l, 1);
        l += __shfl_xor_sync(0xFFFFFFFFu, l, 2);
        inv[e2] = 1.f / l;
    }
    const int tok0 = w * WSZ + qt * 64 + wm * 16 + (lane >> 2);
    const int cb   = h * DHEAD + (lane & 3) * 2;
    #pragma unroll
    for (int nt = 0; nt < 8; nt++) {
        #pragma unroll
        for (int e2 = 0; e2 < 2; e2++) {
            int tok = tok0 + e2 * 8;
            float a = Oacc[nt][e2 * 2]     * inv[e2];
            float b = Oacc[nt][e2 * 2 + 1] * inv[e2];
            float ha = bf16r(a), hb = bf16r(b);
            size_t o = (size_t)tok * INNER + cb + nt * 8;
            *(uint32_t*)(athi + o) = pack_bf2(ha, hb);
            *(uint32_t*)(atlo + o) = pack_bf2(a - ha, b - hb);
        }
    }
}

// ---------------------------------------------------------------------------
// Host-side dispatch
// ---------------------------------------------------------------------------
static __nv_bfloat16 *BHI, *BLO;

#define SMEM64  (2 * (2 * 64  * 80 + 2 * BTILE_BYTES))   // 61440
#define SMEM128 (2 * (2 * 128 * 80 + 2 * BTILE_BYTES))   // 81920

static void gemm(int flags, const __nv_bfloat16* Ahi, const __nv_bfloat16* Alo,
                 const float* B, const float* bias, const float* rbias,
                 const float* Xm, int ldx, const float* resid,
                 float* C, __nv_bfloat16* Chi, __nv_bfloat16* Clo,
                 int M, int N, int K) {
    tspB_k<<<dim3(N / 32, K / 32), 256>>>(B, BHI, BLO, K, N);
    if (N <= 1536) {
        dim3 grid(N / 128, M / 64);
        switch (flags) {
            case 0:
                gemm_bf3<0, 64><<<grid, 256, SMEM64>>>(Ahi, Alo, BHI, BLO, bias, rbias, Xm, ldx, resid, C, Chi, Clo, M, N, K); break;
            case F_BIAS | F_RES:
                gemm_bf3<F_BIAS | F_RES, 64><<<grid, 256, SMEM64>>>(Ahi, Alo, BHI, BLO, bias, rbias, Xm, ldx, resid, C, Chi, Clo, M, N, K); break;
        }
    } else {
        dim3 grid(N / 128, M / 128);
        switch (flags) {
            case F_BIAS | F_GELU:
                gemm_bf3<F_BIAS | F_GELU, 128><<<grid, 256, SMEM128>>>(Ahi, Alo, BHI, BLO, bias, rbias, Xm, ldx, resid, C, Chi, Clo, M, N, K); break;
            case F_BIAS | F_GELU | F_SPLIT | F_NOC:
                gemm_bf3<F_BIAS | F_GELU | F_SPLIT | F_NOC, 128><<<grid, 256, SMEM128>>>(Ahi, Alo, BHI, BLO, bias, rbias, Xm, ldx, resid, C, Chi, Clo, M, N, K); break;
            case F_ROWB | F_MULX | F_SPLIT | F_NOC:
                gemm_bf3<F_ROWB | F_MULX | F_SPLIT | F_NOC, 128><<<grid, 256, SMEM128>>>(Ahi, Alo, BHI, BLO, bias, rbias, Xm, ldx, resid, C, Chi, Clo, M, N, K); break;
            case F_BIAS | F_SPLIT | F_NOC:
                gemm_bf3<F_BIAS | F_SPLIT | F_NOC, 128><<<grid, 256, SMEM128>>>(Ahi, Alo, BHI, BLO, bias, rbias, Xm, ldx, resid, C, Chi, Clo, M, N, K); break;
        }
    }
}

extern "C" void kernel_launch(void* const* d_in, const int* in_sizes, int n_in,
                              void* d_out, int out_size) {
    (void)in_sizes; (void)n_in;
    const int*   tokens   = (const int*)  d_in[0];
    const float* embed    = (const float*)d_in[1];
    const float* attn_ln  = (const float*)d_in[2];
    const float* attn_qkv = (const float*)d_in[3];
    const float* attn_ow  = (const float*)d_in[4];
    const float* attn_ob  = (const float*)d_in[5];
    const float* ff_ln    = (const float*)d_in[6];
    const float* ff_w1    = (const float*)d_in[7];
    const float* ff_b1    = (const float*)d_in[8];
    const float* ff_w2    = (const float*)d_in[9];
    const float* ff_b2    = (const float*)d_in[10];
    const float* gl_ln    = (const float*)d_in[11];
    const float* g_win    = (const float*)d_in[12];
    const float* g_bin    = (const float*)d_in[13];
    const float* g_sln    = (const float*)d_in[14];
    const float* g_sw     = (const float*)d_in[15];
    const float* g_sb     = (const float*)d_in[16];
    const float* g_sow    = (const float*)d_in[17];
    const float* g_sob    = (const float*)d_in[18];
    const float* g_pow    = (const float*)d_in[19];
    const float* g_pob    = (const float*)d_in[20];
    const float* fin_ln   = (const float*)d_in[21];
    const float* head_w   = (const float*)d_in[22];
    const float* head_b   = (const float*)d_in[23];
    float* out = (float*)d_out;
    (void)out_size;

    float *X, *XN, *QKV, *H, *GT, *TP;
    __nv_bfloat16 *XNHI, *XNLO, *HHI, *HLO, *ATHI, *ATLO, *TPHI, *TPLO,
                  *G2HI, *G2LO, *SWHI, *SWLO;
    cudaGetSymbolAddress((void**)&X,    g_x);
    cudaGetSymbolAddress((void**)&XN,   g_xn);
    cudaGetSymbolAddress((void**)&QKV,  g_qkv);
    cudaGetSymbolAddress((void**)&H,    g_h);
    cudaGetSymbolAddress((void**)&GT,   g_gt);
    cudaGetSymbolAddress((void**)&TP,   g_tp);
    cudaGetSymbolAddress((void**)&XNHI, g_xnhi);
    cudaGetSymbolAddress((void**)&XNLO, g_xnlo);
    cudaGetSymbolAddress((void**)&HHI,  g_hhi);
    cudaGetSymbolAddress((void**)&HLO,  g_hlo);
    cudaGetSymbolAddress((void**)&ATHI, g_athi);
    cudaGetSymbolAddress((void**)&ATLO, g_atlo);
    cudaGetSymbolAddress((void**)&TPHI, g_tphi);
    cudaGetSymbolAddress((void**)&TPLO, g_tplo);
    cudaGetSymbolAddress((void**)&G2HI, g_g2hi);
    cudaGetSymbolAddress((void**)&G2LO, g_g2lo);
    cudaGetSymbolAddress((void**)&SWHI, g_swhi);
    cudaGetSymbolAddress((void**)&SWLO, g_swlo);
    cudaGetSymbolAddress((void**)&BHI,  g_bhi);
    cudaGetSymbolAddress((void**)&BLO,  g_blo);

    cudaFuncSetAttribute((const void*)gemm_bf3<0, 64>, cudaFuncAttributeMaxDynamicSharedMemorySize, SMEM64);
    cudaFuncSetAttribute((const void*)gemm_bf3<F_BIAS | F_RES, 64>, cudaFuncAttributeMaxDynamicSharedMemorySize, SMEM64);
    cudaFuncSetAttribute((const void*)gemm_bf3<F_BIAS | F_GELU, 128>, cudaFuncAttributeMaxDynamicSharedMemorySize, SMEM128);
    cudaFuncSetAttribute((const void*)gemm_bf3<F_BIAS | F_GELU | F_SPLIT | F_NOC, 128>, cudaFuncAttributeMaxDynamicSharedMemorySize, SMEM128);
    cudaFuncSetAttribute((const void*)gemm_bf3<F_ROWB | F_MULX | F_SPLIT | F_NOC, 128>, cudaFuncAttributeMaxDynamicSharedMemorySize, SMEM128);
    cudaFuncSetAttribute((const void*)gemm_bf3<F_BIAS | F_SPLIT | F_NOC, 128>, cudaFuncAttributeMaxDynamicSharedMemorySize, SMEM128);
    cudaFuncSetAttribute((const void*)attn_tc, cudaFuncAttributeMaxDynamicSharedMemorySize, ATT_SMEM);

    embed_kernel<<<N_TOK, 256>>>(tokens, embed, X);

    for (int l = 0; l < DEPTH; l++) {
        const float* al = attn_ln  + (size_t)l * DIM;
        const float* aq = attn_qkv + (size_t)l * DIM * 3 * INNER;
        const float* aw = attn_ow  + (size_t)l * INNER * DIM;
        const float* ab = attn_ob  + (size_t)l * DIM;
        const float* fl = ff_ln    + (size_t)l * DIM;
        const float* f1 = ff_w1    + (size_t)l * DIM * DFF;
        const float* b1 = ff_b1    + (size_t)l * DFF;
        const float* f2 = ff_w2    + (size_t)l * DFF * DIM;
        const float* b2 = ff_b2    + (size_t)l * DIM;

        ln_kernel<<<N_TOK, 256>>>(X, DIM, al, nullptr, XNHI, XNLO, DIM, DIM);
        gemm(0, XNHI, XNLO, aq, nullptr, nullptr, nullptr, 0, nullptr,
             QKV, nullptr, nullptr, N_TOK, 3 * INNER, DIM);
        attn_tc<<<dim3(8, 4, NHEAD), 128, ATT_SMEM>>>(QKV, ATHI, ATLO);
        gemm(F_BIAS | F_RES, ATHI, ATLO, aw, ab, nullptr, nullptr, 0, X,
             X, nullptr, nullptr, N_TOK, DIM, INNER);

        ln_kernel<<<N_TOK, 256>>>(X, DIM, fl, nullptr, XNHI, XNLO, DIM, DIM);
        gemm(F_BIAS | F_GELU | F_SPLIT | F_NOC, XNHI, XNLO, f1, b1, nullptr, nullptr, 0, nullptr,
             H, HHI, HLO, N_TOK, DFF, DIM);
        gemm(F_BIAS | F_RES, HHI, HLO, f2, b2, nullptr, nullptr, 0, X,
             X, nullptr, nullptr, N_TOK, DIM, DFF);
    }

    for (int g = 0; g < GDEPTH; g++) {
        const float* gl  = gl_ln + (size_t)g * DIM;
        const float* wi  = g_win + (size_t)g * DIM * DFF;
        const float* bi  = g_bin + (size_t)g * DFF;
        const float* sl  = g_sln + (size_t)g * HALF;
        const float* sw  = g_sw  + (size_t)g * N_TOK * N_TOK;
        const float* sb  = g_sb  + (size_t)g * N_TOK;
        const float* so  = g_sow + (size_t)g * HALF * HALF;
        const float* sob = g_sob + (size_t)g * HALF;
        const float* po  = g_pow + (size_t)g * HALF * DIM;
        const float* pob = g_pob + (size_t)g * DIM;

        ln_kernel<<<N_TOK, 256>>>(X, DIM, gl, nullptr, XNHI, XNLO, DIM, DIM);
        gemm(F_BIAS | F_GELU, XNHI, XNLO, wi, bi, nullptr, nullptr, 0, nullptr,
             H, nullptr, nullptr, N_TOK, DFF, DIM);
        ln_kernel<<<N_TOK, 256>>>(H + HALF, DFF, sl, GT, nullptr, nullptr, HALF, HALF);
        splitA_k<<<(N_TOK * N_TOK / 4 + 255) / 256, 256>>>(sw, SWHI, SWLO,
                                                           N_TOK * N_TOK, N_TOK, 1);
        gemm(F_ROWB | F_MULX | F_SPLIT | F_NOC, SWHI, SWLO, GT, nullptr, sb, H, DFF, nullptr,
             TP, TPHI, TPLO, N_TOK, HALF, N_TOK);
        gemm(F_BIAS | F_SPLIT | F_NOC, TPHI, TPLO, so, sob, nullptr, nullptr, 0, nullptr,
             GT, G2HI, G2LO, N_TOK, HALF, HALF);
        gemm(F_BIAS | F_RES, G2HI, G2LO, po, pob, nullptr, nullptr, 0, X,
             X, nullptr, nullptr, N_TOK, DIM, HALF);
    }

    ln_kernel<<<N_TOK, 256>>>(X, DIM, fin_ln, XN, nullptr, nullptr, DIM, DIM);
    gemm_head<<<dim3(1, N_TOK / 128), 256>>>(XN, head_w, head_b, out, N_TOK, VOCAB, DIM);
}

// round 16
// speedup vs baseline: 1.2545x; 1.0642x over previous
#include <cuda_runtime.h>
#include <cuda_bf16.h>
#include <cstdint>

// ---------------------------------------------------------------------------
// Problem constants
// ---------------------------------------------------------------------------
#define N_TOK 2048
#define DIM   1024
#define DFF   4096
#define HALF  2048
#define INNER 512
#define DEPTH 6
#define GDEPTH 2
#define VOCAB 32
#define WSZ   512
#define NHEAD 8
#define DHEAD 64

// ---------------------------------------------------------------------------
// Scratch (device globals — no allocation allowed)
// ---------------------------------------------------------------------------
__device__ float g_x  [N_TOK * DIM];
__device__ float g_xn [N_TOK * DIM];
__device__ float g_qkv[N_TOK * 3 * INNER];
__device__ float g_h  [N_TOK * DFF];
__device__ float g_gt [N_TOK * HALF];
__device__ float g_tp [N_TOK * HALF];
// bf16 split buffers
__device__ __nv_bfloat16 g_xnhi[N_TOK * DIM],   g_xnlo[N_TOK * DIM];
__device__ __nv_bfloat16 g_hhi [N_TOK * DFF],   g_hlo [N_TOK * DFF];
__device__ __nv_bfloat16 g_athi[N_TOK * INNER], g_atlo[N_TOK * INNER];
__device__ __nv_bfloat16 g_tphi[N_TOK * HALF],  g_tplo[N_TOK * HALF];
__device__ __nv_bfloat16 g_g2hi[N_TOK * HALF],  g_g2lo[N_TOK * HALF];
__device__ __nv_bfloat16 g_swhi[N_TOK * N_TOK], g_swlo[N_TOK * N_TOK];
__device__ __nv_bfloat16 g_bhi [4 * 1024 * 1024], g_blo[4 * 1024 * 1024];

// ---------------------------------------------------------------------------
// Helpers
// ---------------------------------------------------------------------------
__device__ __forceinline__ float gelu_f(float x) {
    const float c = 0.7978845608028654f;
    float t = tanhf(c * (x + 0.044715f * x * x * x));
    return 0.5f * x * (1.0f + t);
}

__device__ __forceinline__ uint32_t s2u(const void* p) {
    uint32_t a;
    asm("{ .reg .u64 t; cvta.to.shared.u64 t, %1; cvt.u32.u64 %0, t; }"
        : "=r"(a) : "l"(p));
    return a;
}

#define CP_ASYNC16(dst, src) \
    asm volatile("cp.async.cg.shared.global [%0], [%1], 16;" :: "r"(dst), "l"(src))
#define CP_COMMIT() asm volatile("cp.async.commit_group;" ::: "memory")
#define CP_WAIT0()  asm volatile("cp.async.wait_group 0;" ::: "memory")

#define LDSM4(r, addr) \
    asm volatile("ldmatrix.sync.aligned.m8n8.x4.shared.b16 {%0,%1,%2,%3}, [%4];" \
                 : "=r"((r)[0]), "=r"((r)[1]), "=r"((r)[2]), "=r"((r)[3]) : "r"(addr))

#define LDSM4T(r, addr) \
    asm volatile("ldmatrix.sync.aligned.m8n8.x4.trans.shared.b16 {%0,%1,%2,%3}, [%4];" \
                 : "=r"((r)[0]), "=r"((r)[1]), "=r"((r)[2]), "=r"((r)[3]) : "r"(addr))

__device__ __forceinline__ void mma_bf16(float* c, const uint32_t* a, const uint32_t* b) {
    asm volatile(
        "mma.sync.aligned.m16n8k16.row.col.f32.bf16.bf16.f32 "
        "{%0,%1,%2,%3}, {%4,%5,%6,%7}, {%8,%9}, {%0,%1,%2,%3};"
        : "+f"(c[0]), "+f"(c[1]), "+f"(c[2]), "+f"(c[3])
        : "r"(a[0]), "r"(a[1]), "r"(a[2]), "r"(a[3]), "r"(b[0]), "r"(b[1]));
}

__device__ __forceinline__ uint32_t pack_bf2(float a, float b) {
    __nv_bfloat162 h = __floats2bfloat162_rn(a, b);
    return *(uint32_t*)&h;
}
__device__ __forceinline__ float bf16r(float v) {
    return __bfloat162float(__float2bfloat16(v));
}

// ---------------------------------------------------------------------------
// Embedding gather
// ---------------------------------------------------------------------------
__global__ void embed_kernel(const int* __restrict__ tok,
                             const float* __restrict__ emb,
                             float* __restrict__ x) {
    int row = blockIdx.x;
    int t = tok[row];
    const float4* src = (const float4*)(emb + (size_t)t * DIM);
    float4* dst = (float4*)(x + (size_t)row * DIM);
    for (int i = threadIdx.x; i < DIM / 4; i += blockDim.x) dst[i] = src[i];
}

// ---------------------------------------------------------------------------
// LayerNorm: optional fp32 out and/or bf16 hi/lo out.
// ---------------------------------------------------------------------------
__global__ void __launch_bounds__(256) ln_kernel(const float* __restrict__ src, int lds,
                                                 const float* __restrict__ gamma,
                                                 float* __restrict__ dstF,
                                                 __nv_bfloat16* __restrict__ hi,
                                                 __nv_bfloat16* __restrict__ lo,
                                                 int ldd, int D) {
    int row = blockIdx.x;
    const float* x = src + (size_t)row * lds;
    float s = 0.f, s2 = 0.f;
    for (int i = threadIdx.x; i < D; i += 256) {
        float v = x[i];
        s += v; s2 += v * v;
    }
    __shared__ float sh[64];
    #pragma unroll
    for (int o = 16; o; o >>= 1) {
        s  += __shfl_xor_sync(0xFFFFFFFFu, s,  o);
        s2 += __shfl_xor_sync(0xFFFFFFFFu, s2, o);
    }
    int warp = threadIdx.x >> 5, lane = threadIdx.x & 31;
    if (lane == 0) { sh[warp] = s; sh[32 + warp] = s2; }
    __syncthreads();
    if (warp == 0) {
        s  = (lane < 8) ? sh[lane]      : 0.f;
        s2 = (lane < 8) ? sh[32 + lane] : 0.f;
        #pragma unroll
        for (int o = 4; o; o >>= 1) {
            s  += __shfl_xor_sync(0xFFFFFFFFu, s,  o);
            s2 += __shfl_xor_sync(0xFFFFFFFFu, s2, o);
        }
        if (lane == 0) {
            float mean = s / D;
            float var  = s2 / D - mean * mean;
            sh[0] = mean;
            sh[1] = rsqrtf(var + 1e-5f);
        }
    }
    __syncthreads();
    float mean = sh[0], rstd = sh[1];
    for (int i = threadIdx.x * 2; i < D; i += 512) {
        float v0 = (x[i]     - mean) * rstd * gamma[i];
        float v1 = (x[i + 1] - mean) * rstd * gamma[i + 1];
        size_t o = (size_t)row * ldd + i;
        if (dstF) { dstF[o] = v0; dstF[o + 1] = v1; }
        if (hi) {
            float h0 = bf16r(v0), h1 = bf16r(v1);
            *(uint32_t*)(hi + o) = pack_bf2(h0, h1);
            *(uint32_t*)(lo + o) = pack_bf2(v0 - h0, v1 - h1);
        }
    }
}

// ---------------------------------------------------------------------------
// Split A (fp32 -> bf16 hi/lo) with tril mask — only used for g_sw.
// ---------------------------------------------------------------------------
__global__ void __launch_bounds__(256) splitA_k(const float* __restrict__ A,
                                                __nv_bfloat16* __restrict__ hi,
                                                __nv_bfloat16* __restrict__ lo,
                                                int MK, int K, int tril) {
    int i4 = (blockIdx.x * 256 + threadIdx.x) * 4;
    if (i4 >= MK) return;
    float4 v = *(const float4*)(A + i4);
    float vv[4] = {v.x, v.y, v.z, v.w};
    if (tril) {
        int m = i4 / K, k = i4 - m * K;
        #pragma unroll
        for (int e = 0; e < 4; e++)
            if (k + e > m) vv[e] = 0.f;
    }
    float hf[4];
    #pragma unroll
    for (int e = 0; e < 4; e++) hf[e] = bf16r(vv[e]);
    uint2 ho, lo2;
    ho.x  = pack_bf2(hf[0], hf[1]); ho.y  = pack_bf2(hf[2], hf[3]);
    lo2.x = pack_bf2(vv[0] - hf[0], vv[1] - hf[1]);
    lo2.y = pack_bf2(vv[2] - hf[2], vv[3] - hf[3]);
    *(uint2*)(hi + i4) = ho;
    *(uint2*)(lo + i4) = lo2;
}

// ---------------------------------------------------------------------------
// Transpose + split B: B[K][N] fp32 -> Bt hi/lo bf16 [N][K]
// ---------------------------------------------------------------------------
__global__ void __launch_bounds__(256) tspB_k(const float* __restrict__ B,
                                              __nv_bfloat16* __restrict__ hi,
                                              __nv_bfloat16* __restrict__ lo,
                                              int K, int N) {
    __shared__ float sh[32][33];
    int nt = blockIdx.x * 32, kt = blockIdx.y * 32;
    int tx = threadIdx.x & 31, ty = threadIdx.x >> 5;
    #pragma unroll
    for (int j = 0; j < 32; j += 8)
        sh[ty + j][tx] = B[(size_t)(kt + ty + j) * N + nt + tx];
    __syncthreads();
    #pragma unroll
    for (int j = 0; j < 32; j += 8) {
        float v = sh[tx][ty + j];
        float h = bf16r(v);
        size_t o = (size_t)(nt + ty + j) * K + kt + tx;
        hi[o] = __float2bfloat16(h);
        lo[o] = __float2bfloat16(v - h);
    }
}

// ---------------------------------------------------------------------------
// Split-bf16 3-term tensor-core GEMM, templated on (BM, BK).
// BM=64 uses BK=64 (144B rows, 2 CTAs/SM, half the barriers);
// BM=128 uses BK=32 (80B rows, 2 CTAs/SM).
// Single-sync mainloop; F_NOC skips dead fp32 C store.
// ---------------------------------------------------------------------------
enum { F_BIAS = 1, F_GELU = 2, F_RES = 4, F_MULX = 16, F_ROWB = 32, F_SPLIT = 64,
       F_NOC = 128 };

template <int FLAGS, int BM>
__global__ void __launch_bounds__(256, 2) gemm_bf3(
    const __nv_bfloat16* __restrict__ Ahi, const __nv_bfloat16* __restrict__ Alo,
    const __nv_bfloat16* __restrict__ Bhi, const __nv_bfloat16* __restrict__ Blo,
    const float* __restrict__ bias, const float* __restrict__ rbias,
    const float* __restrict__ Xm, int ldx,
    const float* __restrict__ resid,
    float* __restrict__ C,
    __nv_bfloat16* __restrict__ Chi, __nv_bfloat16* __restrict__ Clo,
    int M, int N, int K) {

    constexpr int BK    = (BM == 64) ? 64 : 32;
    constexpr int KROW  = BK * 2 + 16;          // bytes per SMEM row (padded)
    constexpr int ATILE = BM * KROW;
    constexpr int BTILE = 128 * KROW;
    constexpr int STAGE = 2 * ATILE + 2 * BTILE;
    constexpr int UP    = (BM == 128) ? 4 : 2;  // 16-col uptiles per warp
    constexpr int CHR   = BK / 8;               // 16B chunks per row
    constexpr int NKS   = BK / 16;              // k16 steps per stage

    extern __shared__ char dsm[];
    const uint32_t smem_base = s2u(dsm);

    const int tid  = threadIdx.x;
    const int wid  = tid >> 5;
    const int lane = tid & 31;
    const int wm   = (BM == 128) ? (wid >> 1) : (wid & 1);
    const int wn   = (BM == 128) ? (wid & 1)  : (wid >> 1);
    const int bm = blockIdx.y * BM, bn = blockIdx.x * 128;

    float acc[2][2 * UP][4];
    #pragma unroll
    for (int i = 0; i < 2; i++)
        #pragma unroll
        for (int j = 0; j < 2 * UP; j++)
            #pragma unroll
            for (int e = 0; e < 4; e++) acc[i][j][e] = 0.f;

    const __nv_bfloat16* bases[4] = {
        Ahi + (size_t)bm * K, Alo + (size_t)bm * K,
        Bhi + (size_t)bn * K, Blo + (size_t)bn * K };

    const int mi  = lane >> 3;
    const int lr8 = lane & 7;
    const int a_off = ((mi & 1) * 8 + lr8) * KROW + (mi >> 1) * 16;
    const int b_off = ((mi >> 1) * 8 + lr8) * KROW + (mi & 1) * 16;

    const int nK = K / BK;

    #define LOAD_STAGE(s, kt) do {                                             \
        uint32_t sb_ = smem_base + (s) * STAGE;                                \
        int kc_ = (kt) * BK;                                                   \
        _Pragma("unroll")                                                      \
        for (int t = 0; t < 2 * BM * CHR / 256; t++) {                         \
            int w = t * 256 + tid;                                             \
            int tile = w / (BM * CHR);                                         \
            int rr = (w % (BM * CHR)) / CHR, ch = w % CHR;                     \
            const char* src = (const char*)(bases[tile] + (size_t)rr * K + kc_ + ch * 8); \
            uint32_t dst = sb_ + tile * ATILE + rr * KROW + ch * 16;           \
            CP_ASYNC16(dst, src);                                              \
        }                                                                      \
        _Pragma("unroll")                                                      \
        for (int t = 0; t < 2 * 128 * CHR / 256; t++) {                        \
            int w = t * 256 + tid;                                             \
            int bt = w / (128 * CHR);                                          \
            int rr = (w % (128 * CHR)) / CHR, ch = w % CHR;                    \
            const char* src = (const char*)(bases[2 + bt] + (size_t)rr * K + kc_ + ch * 8); \
            uint32_t dst = sb_ + 2 * ATILE + bt * BTILE + rr * KROW + ch * 16; \
            CP_ASYNC16(dst, src);                                              \
        }                                                                      \
        CP_COMMIT();                                                           \
    } while (0)

    LOAD_STAGE(0, 0);

    for (int kt = 0; kt < nK; kt++) {
        int s = kt & 1;
        CP_WAIT0();
        __syncthreads();
        if (kt + 1 < nK) LOAD_STAGE(s ^ 1, kt + 1);

        uint32_t TAh = smem_base + s * STAGE;
        uint32_t TAl = TAh + ATILE;
        uint32_t TBh = TAh + 2 * ATILE;
        uint32_t TBl = TBh + BTILE;

        #pragma unroll
        for (int ks = 0; ks < NKS; ks++) {
            uint32_t ah[2][4], al_[2][4];
            #pragma unroll
            for (int mt = 0; mt < 2; mt++) {
                int rb = (wm * 32 + mt * 16) * KROW + ks * 32;
                LDSM4(ah[mt],  TAh + rb + a_off);
                LDSM4(al_[mt], TAl + rb + a_off);
            }
            uint32_t bh[UP][4], bl[UP][4];
            #pragma unroll
            for (int up = 0; up < UP; up++) {
                int rb = (wn * UP * 16 + up * 16) * KROW + ks * 32;
                LDSM4(bh[up], TBh + rb + b_off);
                LDSM4(bl[up], TBl + rb + b_off);
            }
            #pragma unroll
            for (int term = 0; term < 3; term++) {
                #pragma unroll
                for (int mt = 0; mt < 2; mt++) {
                    const uint32_t* A_ = (term == 2) ? al_[mt] : ah[mt];
                    #pragma unroll
                    for (int up = 0; up < UP; up++) {
                        const uint32_t* B_ = (term == 1) ? bl[up] : bh[up];
                        mma_bf16(acc[mt][2 * up],     A_, &B_[0]);
                        mma_bf16(acc[mt][2 * up + 1], A_, &B_[2]);
                    }
                }
            }
        }
    }

    const int r0 = bm + wm * 32 + (lane >> 2);
    const int cb = bn + wn * (UP * 16) + (lane & 3) * 2;
    #pragma unroll
    for (int mt = 0; mt < 2; mt++) {
        #pragma unroll
        for (int nt = 0; nt < 2 * UP; nt++) {
            float* a4 = acc[mt][nt];
            int gm = r0 + mt * 16;
            int gn = cb + nt * 8;
            float vv[4];
            #pragma unroll
            for (int e = 0; e < 4; e++) {
                int rr = gm + (e >> 1) * 8;
                int cc = gn + (e & 1);
                float v = a4[e];
                if (FLAGS & F_BIAS) v += bias[cc];
                if (FLAGS & F_ROWB) v += rbias[rr];
                if (FLAGS & F_GELU) v = gelu_f(v);
                if (FLAGS & F_MULX) v *= Xm[(size_t)rr * ldx + cc];
                if (FLAGS & F_RES)  v += resid[(size_t)rr * N + cc];
                vv[e] = v;
            }
            size_t o0 = (size_t)gm * N + gn;
            size_t o1 = (size_t)(gm + 8) * N + gn;
            if (!(FLAGS & F_NOC)) {
                *(float2*)(C + o0) = make_float2(vv[0], vv[1]);
                *(float2*)(C + o1) = make_float2(vv[2], vv[3]);
            }
            if (FLAGS & F_SPLIT) {
                float h0 = bf16r(vv[0]), h1 = bf16r(vv[1]);
                float h2 = bf16r(vv[2]), h3 = bf16r(vv[3]);
                *(uint32_t*)(Chi + o0) = pack_bf2(h0, h1);
                *(uint32_t*)(Chi + o1) = pack_bf2(h2, h3);
                *(uint32_t*)(Clo + o0) = pack_bf2(vv[0] - h0, vv[1] - h1);
                *(uint32_t*)(Clo + o1) = pack_bf2(vv[2] - h2, vv[3] - h3);
            }
        }
    }
}

// ---------------------------------------------------------------------------
// Exact fp32 SIMT GEMM for the head (N=32)
// ---------------------------------------------------------------------------
__global__ void __launch_bounds__(256) gemm_head(
    const float* __restrict__ A, const float* __restrict__ B,
    const float* __restrict__ bias, float* __restrict__ C,
    int M, int N, int K) {
    __shared__ float As[16][128];
    __shared__ float Bs[16][32];
    const int tid = threadIdx.x;
    const int bm = blockIdx.y * 128;
    const int r = tid >> 1;
    const int cp = (tid & 1) * 16;
    float acc[16];
    #pragma unroll
    for (int j = 0; j < 16; j++) acc[j] = 0.f;

    const int a_row = tid >> 2, a_col = (tid & 3) << 2;
    const int b_row = tid >> 3, b_col = (tid & 7) << 2;

    for (int kt = 0; kt < K; kt += 16) {
        #pragma unroll
        for (int rr = 0; rr < 2; rr++) {
            int lm = a_row + rr * 64;
            float4 v = *(const float4*)(A + (size_t)(bm + lm) * K + kt + a_col);
            As[a_col + 0][lm] = v.x; As[a_col + 1][lm] = v.y;
            As[a_col + 2][lm] = v.z; As[a_col + 3][lm] = v.w;
        }
        if (b_row < 16) {
            float4 v = *(const float4*)(B + (size_t)(kt + b_row) * N + b_col);
            *(float4*)&Bs[b_row][b_col] = v;
        }
        __syncthreads();
        #pragma unroll
        for (int kk = 0; kk < 16; kk++) {
            float a = As[kk][r];
            #pragma unroll
            for (int j = 0; j < 16; j++) acc[j] += a * Bs[kk][cp + j];
        }
        __syncthreads();
    }
    #pragma unroll
    for (int j = 0; j < 16; j++)
        C[(size_t)(bm + r) * N + cp + j] = acc[j] + bias[cp + j];
}

// ---------------------------------------------------------------------------
// Tensor-core flash attention (round-14 winner, unchanged).
// ---------------------------------------------------------------------------
#define AQH 0
#define AQL 9216
#define AKH 18432
#define AKL 27648
#define AVH 36864
#define AVL 46080
#define ATT_SMEM 55296

__global__ void __launch_bounds__(128, 3) attn_tc(const float* __restrict__ qkv,
                                                  __nv_bfloat16* __restrict__ athi,
                                                  __nv_bfloat16* __restrict__ atlo) {
    extern __shared__ char dsm[];
    const uint32_t sb = s2u(dsm);

    const int h  = blockIdx.z;
    const int w  = blockIdx.y;
    const int qt = blockIdx.x;
    const int tid  = threadIdx.x;
    const int wm   = tid >> 5;
    const int lane = tid & 31;
    const int mi   = lane >> 3;
    const int lr8  = lane & 7;

    {
        int row = tid >> 1, halfd = tid & 1;
        int tq = w * WSZ + qt * 64 + row;
        const float4* qp = (const float4*)(qkv + (size_t)tq * (3 * INNER) + h * DHEAD + halfd * 32);
        char* dh = dsm + AQH + row * 144 + halfd * 64;
        char* dl = dsm + AQL + row * 144 + halfd * 64;
        #pragma unroll
        for (int f = 0; f < 8; f++) {
            float4 v = qp[f];
            float a0 = v.x * 0.125f, a1 = v.y * 0.125f, a2 = v.z * 0.125f, a3 = v.w * 0.125f;
            float h0 = bf16r(a0), h1 = bf16r(a1), h2 = bf16r(a2), h3 = bf16r(a3);
            uint2 uh, ul;
            uh.x = pack_bf2(h0, h1); uh.y = pack_bf2(h2, h3);
            ul.x = pack_bf2(a0 - h0, a1 - h1); ul.y = pack_bf2(a2 - h2, a3 - h3);
            *(uint2*)(dh + f * 8) = uh;
            *(uint2*)(dl + f * 8) = ul;
        }
    }
    __syncthreads();

    uint32_t qf_h[4][4], qf_l[4][4];
    {
        uint32_t abase = sb + (wm * 16 + (mi & 1) * 8 + lr8) * 144 + (mi >> 1) * 16;
        #pragma unroll
        for (int ks = 0; ks < 4; ks++) {
            LDSM4(qf_h[ks], abase + AQH + ks * 32);
            LDSM4(qf_l[ks], abase + AQL + ks * 32);
        }
    }

    float Oacc[8][4];
    #pragma unroll
    for (int nt = 0; nt < 8; nt++)
        #pragma unroll
        for (int e = 0; e < 4; e++) Oacc[nt][e] = 0.f;
    float mrow[2] = {-1e30f, -1e30f};
    float lrow[2] = {0.f, 0.f};

    const int i_base = qt * 64 + wm * 16 + (lane >> 2);
    const int nchunk = qt + 9;

    const uint32_t boffKV = ((mi >> 1) * 8 + lr8) * 144 + (mi & 1) * 16;
    const uint32_t toffV  = ((mi & 1) * 8 + lr8) * 144 + (mi >> 1) * 16;

    for (int c = 0; c < nchunk; c++) {
        int j0 = c * 64;
        __syncthreads();

        {
            int row = tid >> 1, halfd = tid & 1;
            int tk = (w - 1) * WSZ + j0 + row;
            const float4* kp = (const float4*)(qkv + (size_t)tk * (3 * INNER) + INNER + h * DHEAD + halfd * 32);
            const float4* vp = kp + INNER / 4;
            char* dkh = dsm + AKH + row * 144 + halfd * 64;
            char* dkl = dsm + AKL + row * 144 + halfd * 64;
            char* dvh = dsm + AVH + row * 144 + halfd * 64;
            char* dvl = dsm + AVL + row * 144 + halfd * 64;
            #pragma unroll
            for (int f = 0; f < 8; f++) {
                float4 kv = make_float4(0.f, 0.f, 0.f, 0.f);
                float4 vv = make_float4(0.f, 0.f, 0.f, 0.f);
                if (tk >= 0) { kv = kp[f]; vv = vp[f]; }
                float kh0 = bf16r(kv.x), kh1 = bf16r(kv.y), kh2 = bf16r(kv.z), kh3 = bf16r(kv.w);
                float vh0 = bf16r(vv.x), vh1 = bf16r(vv.y), vh2 = bf16r(vv.z), vh3 = bf16r(vv.w);
                uint2 u;
                u.x = pack_bf2(kh0, kh1); u.y = pack_bf2(kh2, kh3);
                *(uint2*)(dkh + f * 8) = u;
                u.x = pack_bf2(kv.x - kh0, kv.y - kh1); u.y = pack_bf2(kv.z - kh2, kv.w - kh3);
                *(uint2*)(dkl + f * 8) = u;
                u.x = pack_bf2(vh0, vh1); u.y = pack_bf2(vh2, vh3);
                *(uint2*)(dvh + f * 8) = u;
                u.x = pack_bf2(vv.x - vh0, vv.y - vh1); u.y = pack_bf2(vv.z - vh2, vv.w - vh3);
                *(uint2*)(dvl + f * 8) = u;
            }
        }
        __syncthreads();

        float Sa[8][4];
        #pragma unroll
        for (int nt = 0; nt < 8; nt++)
            #pragma unroll
            for (int e = 0; e < 4; e++) Sa[nt][e] = 0.f;

        #pragma unroll
        for (int ks = 0; ks < 4; ks++) {
            #pragma unroll
            for (int ng = 0; ng < 4; ng++) {
                uint32_t kb = sb + (ng * 16) * 144 + boffKV + ks * 32;
                uint32_t kh4[4], kl4[4];
                LDSM4(kh4, kb + AKH);
                LDSM4(kl4, kb + AKL);
                mma_bf16(Sa[2 * ng],     qf_h[ks], &kh4[0]);
                mma_bf16(Sa[2 * ng],     qf_h[ks], &kl4[0]);
                mma_bf16(Sa[2 * ng],     qf_l[ks], &kh4[0]);
                mma_bf16(Sa[2 * ng + 1], qf_h[ks], &kh4[2]);
                mma_bf16(Sa[2 * ng + 1], qf_h[ks], &kl4[2]);
                mma_bf16(Sa[2 * ng + 1], qf_l[ks], &kh4[2]);
            }
        }

        #pragma unroll
        for (int nt = 0; nt < 8; nt++)
            #pragma unroll
            for (int e = 0; e < 4; e++) {
                int col = j0 + nt * 8 + (lane & 3) * 2 + (e & 1);
                int ri  = i_base + (e >> 1) * 8;
                if (col > ri + WSZ) Sa[nt][e] = -1e30f;
            }

        #pragma unroll
        for (int e2 = 0; e2 < 2; e2++) {
            float mx = -1e30f;
            #pragma unroll
            for (int nt = 0; nt < 8; nt++) {
                mx = fmaxf(mx, Sa[nt][e2 * 2]);
                mx = fmaxf(mx, Sa[nt][e2 * 2 + 1]);
            }
            mx = fmaxf(mx, __shfl_xor_sync(0xFFFFFFFFu, mx, 1));
            mx = fmaxf(mx, __shfl_xor_sync(0xFFFFFFFFu, mx, 2));
            float mnew = fmaxf(mrow[e2], mx);
            float corr = __expf(mrow[e2] - mnew);
            mrow[e2] = mnew;
            lrow[e2] *= corr;
            #pragma unroll
            for (int nt = 0; nt < 8; nt++) {
                Oacc[nt][e2 * 2]     *= corr;
                Oacc[nt][e2 * 2 + 1] *= corr;
            }
            float psum = 0.f;
            #pragma unroll
            for (int nt = 0; nt < 8; nt++) {
                float p0 = __expf(Sa[nt][e2 * 2]     - mnew);
                float p1 = __expf(Sa[nt][e2 * 2 + 1] - mnew);
                Sa[nt][e2 * 2]     = p0;
                Sa[nt][e2 * 2 + 1] = p1;
                psum += p0 + p1;
            }
            lrow[e2] += psum;
        }

        #pragma unroll
        for (int kt = 0; kt < 4; kt++) {
            uint32_t ph[4], pl[4];
            #pragma unroll
            for (int half = 0; half < 2; half++) {
                float s0 = Sa[2 * kt + half][0], s1 = Sa[2 * kt + half][1];
                float s2 = Sa[2 * kt + half][2], s3 = Sa[2 * kt + half][3];
                float h0 = bf16r(s0), h1 = bf16r(s1), h2 = bf16r(s2), h3 = bf16r(s3);
                ph[2 * half]     = pack_bf2(h0, h1);
                ph[2 * half + 1] = pack_bf2(h2, h3);
                pl[2 * half]     = pack_bf2(s0 - h0, s1 - h1);
                pl[2 * half + 1] = pack_bf2(s2 - h2, s3 - h3);
            }
            #pragma unroll
            for (int vt = 0; vt < 4; vt++) {
                uint32_t vb = sb + (kt * 16) * 144 + toffV + vt * 32;
                uint32_t vh4[4], vl4[4];
                LDSM4T(vh4, vb + AVH);
                LDSM4T(vl4, vb + AVL);
                mma_bf16(Oacc[2 * vt],     ph, &vh4[0]);
                mma_bf16(Oacc[2 * vt],     pl, &vh4[0]);
                mma_bf16(Oacc[2 * vt],     ph, &vl4[0]);
                mma_bf16(Oacc[2 * vt + 1], ph, &vh4[2]);
                mma_bf16(Oacc[2 * vt + 1], pl, &vh4[2]);
                mma_bf16(Oacc[2 * vt + 1], ph, &vl4[2]);
            }
        }
    }

    float inv[2];
    #pragma unroll
    for (int e2 = 0; e2 < 2; e2++) {
        float l = lrow[e2];
        l += __shfl_xor_sync(0xFFFFFFFFu, l, 1);
        l += __shfl_xor_sync(0xFFFFFFFFu, l, 2);
        inv[e2] = 1.f / l;
    }
    const int tok0 = w * WSZ + qt * 64 + wm * 16 + (lane >> 2);
    const int cb   = h * DHEAD + (lane & 3) * 2;
    #pragma unroll
    for (int nt = 0; nt < 8; nt++) {
        #pragma unroll
        for (int e2 = 0; e2 < 2; e2++) {
            int tok = tok0 + e2 * 8;
            float a = Oacc[nt][e2 * 2]     * inv[e2];
            float b = Oacc[nt][e2 * 2 + 1] * inv[e2];
            float ha = bf16r(a), hb = bf16r(b);
            size_t o = (size_t)tok * INNER + cb + nt * 8;
            *(uint32_t*)(athi + o) = pack_bf2(ha, hb);
            *(uint32_t*)(atlo + o) = pack_bf2(a - ha, b - hb);
        }
    }
}

// ---------------------------------------------------------------------------
// Host-side dispatch
// ---------------------------------------------------------------------------
static __nv_bfloat16 *BHI, *BLO;

#define SMEM64  (2 * (2 * 64 * 144 + 2 * 128 * 144))   // 110592
#define SMEM128 (2 * (2 * 128 * 80 + 2 * 128 * 80))    // 81920

static void gemm(int flags, const __nv_bfloat16* Ahi, const __nv_bfloat16* Alo,
                 const float* B, const float* bias, const float* rbias,
                 const float* Xm, int ldx, const float* resid,
                 float* C, __nv_bfloat16* Chi, __nv_bfloat16* Clo,
                 int M, int N, int K) {
    tspB_k<<<dim3(N / 32, K / 32), 256>>>(B, BHI, BLO, K, N);
    if (N <= 1536) {
        dim3 grid(N / 128, M / 64);
        switch (flags) {
            case 0:
                gemm_bf3<0, 64><<<grid, 256, SMEM64>>>(Ahi, Alo, BHI, BLO, bias, rbias, Xm, ldx, resid, C, Chi, Clo, M, N, K); break;
            case F_BIAS | F_RES:
                gemm_bf3<F_BIAS | F_RES, 64><<<grid, 256, SMEM64>>>(Ahi, Alo, BHI, BLO, bias, rbias, Xm, ldx, resid, C, Chi, Clo, M, N, K); break;
        }
    } else {
        dim3 grid(N / 128, M / 128);
        switch (flags) {
            case F_BIAS | F_GELU:
                gemm_bf3<F_BIAS | F_GELU, 128><<<grid, 256, SMEM128>>>(Ahi, Alo, BHI, BLO, bias, rbias, Xm, ldx, resid, C, Chi, Clo, M, N, K); break;
            case F_BIAS | F_GELU | F_SPLIT | F_NOC:
                gemm_bf3<F_BIAS | F_GELU | F_SPLIT | F_NOC, 128><<<grid, 256, SMEM128>>>(Ahi, Alo, BHI, BLO, bias, rbias, Xm, ldx, resid, C, Chi, Clo, M, N, K); break;
            case F_ROWB | F_MULX | F_SPLIT | F_NOC:
                gemm_bf3<F_ROWB | F_MULX | F_SPLIT | F_NOC, 128><<<grid, 256, SMEM128>>>(Ahi, Alo, BHI, BLO, bias, rbias, Xm, ldx, resid, C, Chi, Clo, M, N, K); break;
            case F_BIAS | F_SPLIT | F_NOC:
                gemm_bf3<F_BIAS | F_SPLIT | F_NOC, 128><<<grid, 256, SMEM128>>>(Ahi, Alo, BHI, BLO, bias, rbias, Xm, ldx, resid, C, Chi, Clo, M, N, K); break;
        }
    }
}

extern "C" void kernel_launch(void* const* d_in, const int* in_sizes, int n_in,
                              void* d_out, int out_size) {
    (void)in_sizes; (void)n_in;
    const int*   tokens   = (const int*)  d_in[0];
    const float* embed    = (const float*)d_in[1];
    const float* attn_ln  = (const float*)d_in[2];
    const float* attn_qkv = (const float*)d_in[3];
    const float* attn_ow  = (const float*)d_in[4];
    const float* attn_ob  = (const float*)d_in[5];
    const float* ff_ln    = (const float*)d_in[6];
    const float* ff_w1    = (const float*)d_in[7];
    const float* ff_b1    = (const float*)d_in[8];
    const float* ff_w2    = (const float*)d_in[9];
    const float* ff_b2    = (const float*)d_in[10];
    const float* gl_ln    = (const float*)d_in[11];
    const float* g_win    = (const float*)d_in[12];
    const float* g_bin    = (const float*)d_in[13];
    const float* g_sln    = (const float*)d_in[14];
    const float* g_sw     = (const float*)d_in[15];
    const float* g_sb     = (const float*)d_in[16];
    const float* g_sow    = (const float*)d_in[17];
    const float* g_sob    = (const float*)d_in[18];
    const float* g_pow    = (const float*)d_in[19];
    const float* g_pob    = (const float*)d_in[20];
    const float* fin_ln   = (const float*)d_in[21];
    const float* head_w   = (const float*)d_in[22];
    const float* head_b   = (const float*)d_in[23];
    float* out = (float*)d_out;
    (void)out_size;

    float *X, *XN, *QKV, *H, *GT, *TP;
    __nv_bfloat16 *XNHI, *XNLO, *HHI, *HLO, *ATHI, *ATLO, *TPHI, *TPLO,
                  *G2HI, *G2LO, *SWHI, *SWLO;
    cudaGetSymbolAddress((void**)&X,    g_x);
    cudaGetSymbolAddress((void**)&XN,   g_xn);
    cudaGetSymbolAddress((void**)&QKV,  g_qkv);
    cudaGetSymbolAddress((void**)&H,    g_h);
    cudaGetSymbolAddress((void**)&GT,   g_gt);
    cudaGetSymbolAddress((void**)&TP,   g_tp);
    cudaGetSymbolAddress((void**)&XNHI, g_xnhi);
    cudaGetSymbolAddress((void**)&XNLO, g_xnlo);
    cudaGetSymbolAddress((void**)&HHI,  g_hhi);
    cudaGetSymbolAddress((void**)&HLO,  g_hlo);
    cudaGetSymbolAddress((void**)&ATHI, g_athi);
    cudaGetSymbolAddress((void**)&ATLO, g_atlo);
    cudaGetSymbolAddress((void**)&TPHI, g_tphi);
    cudaGetSymbolAddress((void**)&TPLO, g_tplo);
    cudaGetSymbolAddress((void**)&G2HI, g_g2hi);
    cudaGetSymbolAddress((void**)&G2LO, g_g2lo);
    cudaGetSymbolAddress((void**)&SWHI, g_swhi);
    cudaGetSymbolAddress((void**)&SWLO, g_swlo);
    cudaGetSymbolAddress((void**)&BHI,  g_bhi);
    cudaGetSymbolAddress((void**)&BLO,  g_blo);

    cudaFuncSetAttribute((const void*)gemm_bf3<0, 64>, cudaFuncAttributeMaxDynamicSharedMemorySize, SMEM64);
    cudaFuncSetAttribute((const void*)gemm_bf3<F_BIAS | F_RES, 64>, cudaFuncAttributeMaxDynamicSharedMemorySize, SMEM64);
    cudaFuncSetAttribute((const void*)gemm_bf3<F_BIAS | F_GELU, 128>, cudaFuncAttributeMaxDynamicSharedMemorySize, SMEM128);
    cudaFuncSetAttribute((const void*)gemm_bf3<F_BIAS | F_GELU | F_SPLIT | F_NOC, 128>, cudaFuncAttributeMaxDynamicSharedMemorySize, SMEM128);
    cudaFuncSetAttribute((const void*)gemm_bf3<F_ROWB | F_MULX | F_SPLIT | F_NOC, 128>, cudaFuncAttributeMaxDynamicSharedMemorySize, SMEM128);
    cudaFuncSetAttribute((const void*)gemm_bf3<F_BIAS | F_SPLIT | F_NOC, 128>, cudaFuncAttributeMaxDynamicSharedMemorySize, SMEM128);
    cudaFuncSetAttribute((const void*)attn_tc, cudaFuncAttributeMaxDynamicSharedMemorySize, ATT_SMEM);

    embed_kernel<<<N_TOK, 256>>>(tokens, embed, X);

    for (int l = 0; l < DEPTH; l++) {
        const float* al = attn_ln  + (size_t)l * DIM;
        const float* aq = attn_qkv + (size_t)l * DIM * 3 * INNER;
        const float* aw = attn_ow  + (size_t)l * INNER * DIM;
        const float* ab = attn_ob  + (size_t)l * DIM;
        const float* fl = ff_ln    + (size_t)l * DIM;
        const float* f1 = ff_w1    + (size_t)l * DIM * DFF;
        const float* b1 = ff_b1    + (size_t)l * DFF;
        const float* f2 = ff_w2    + (size_t)l * DFF * DIM;
        const float* b2 = ff_b2    + (size_t)l * DIM;

        ln_kernel<<<N_TOK, 256>>>(X, DIM, al, nullptr, XNHI, XNLO, DIM, DIM);
        gemm(0, XNHI, XNLO, aq, nullptr, nullptr, nullptr, 0, nullptr,
             QKV, nullptr, nullptr, N_TOK, 3 * INNER, DIM);
        attn_tc<<<dim3(8, 4, NHEAD), 128, ATT_SMEM>>>(QKV, ATHI, ATLO);
        gemm(F_BIAS | F_RES, ATHI, ATLO, aw, ab, nullptr, nullptr, 0, X,
             X, nullptr, nullptr, N_TOK, DIM, INNER);

        ln_kernel<<<N_TOK, 256>>>(X, DIM, fl, nullptr, XNHI, XNLO, DIM, DIM);
        gemm(F_BIAS | F_GELU | F_SPLIT | F_NOC, XNHI, XNLO, f1, b1, nullptr, nullptr, 0, nullptr,
             H, HHI, HLO, N_TOK, DFF, DIM);
        gemm(F_BIAS | F_RES, HHI, HLO, f2, b2, nullptr, nullptr, 0, X,
             X, nullptr, nullptr, N_TOK, DIM, DFF);
    }

    for (int g = 0; g < GDEPTH; g++) {
        const float* gl  = gl_ln + (size_t)g * DIM;
        const float* wi  = g_win + (size_t)g * DIM * DFF;
        const float* bi  = g_bin + (size_t)g * DFF;
        const float* sl  = g_sln + (size_t)g * HALF;
        const float* sw  = g_sw  + (size_t)g * N_TOK * N_TOK;
        const float* sb  = g_sb  + (size_t)g * N_TOK;
        const float* so  = g_sow + (size_t)g * HALF * HALF;
        const float* sob = g_sob + (size_t)g * HALF;
        const float* po  = g_pow + (size_t)g * HALF * DIM;
        const float* pob = g_pob + (size_t)g * DIM;

        ln_kernel<<<N_TOK, 256>>>(X, DIM, gl, nullptr, XNHI, XNLO, DIM, DIM);
        gemm(F_BIAS | F_GELU, XNHI, XNLO, wi, bi, nullptr, nullptr, 0, nullptr,
             H, nullptr, nullptr, N_TOK, DFF, DIM);
        ln_kernel<<<N_TOK, 256>>>(H + HALF, DFF, sl, GT, nullptr, nullptr, HALF, HALF);
        splitA_k<<<(N_TOK * N_TOK / 4 + 255) / 256, 256>>>(sw, SWHI, SWLO,
                                                           N_TOK * N_TOK, N_TOK, 1);
        gemm(F_ROWB | F_MULX | F_SPLIT | F_NOC, SWHI, SWLO, GT, nullptr, sb, H, DFF, nullptr,
             TP, TPHI, TPLO, N_TOK, HALF, N_TOK);
        gemm(F_BIAS | F_SPLIT | F_NOC, TPHI, TPLO, so, sob, nullptr, nullptr, 0, nullptr,
             GT, G2HI, G2LO, N_TOK, HALF, HALF);
        gemm(F_BIAS | F_RES, G2HI, G2LO, po, pob, nullptr, nullptr, 0, X,
             X, nullptr, nullptr, N_TOK, DIM, HALF);
    }

    ln_kernel<<<N_TOK, 256>>>(X, DIM, fin_ln, XN, nullptr, nullptr, DIM, DIM);
    gemm_head<<<dim3(1, N_TOK / 128), 256>>>(XN, head_w, head_b, out, N_TOK, VOCAB, DIM);
}

// round 17
// speedup vs baseline: 1.2665x; 1.0096x over previous
#include <cuda_runtime.h>
#include <cuda_bf16.h>
#include <cstdint>

// ---------------------------------------------------------------------------
// Problem constants
// ---------------------------------------------------------------------------
#define N_TOK 2048
#define DIM   1024
#define DFF   4096
#define HALF  2048
#define INNER 512
#define DEPTH 6
#define GDEPTH 2
#define VOCAB 32
#define WSZ   512
#define NHEAD 8
#define DHEAD 64

// ---------------------------------------------------------------------------
// Scratch (device globals — no allocation allowed)
// ---------------------------------------------------------------------------
__device__ float g_x  [N_TOK * DIM];
__device__ float g_xn [N_TOK * DIM];
__device__ float g_qkv[N_TOK * 3 * INNER];
__device__ float g_h  [N_TOK * DFF];
__device__ float g_gt [N_TOK * HALF];
__device__ float g_tp [N_TOK * HALF];
// bf16 split buffers
__device__ __nv_bfloat16 g_xnhi[N_TOK * DIM],   g_xnlo[N_TOK * DIM];
__device__ __nv_bfloat16 g_hhi [N_TOK * DFF],   g_hlo [N_TOK * DFF];
__device__ __nv_bfloat16 g_athi[N_TOK * INNER], g_atlo[N_TOK * INNER];
__device__ __nv_bfloat16 g_tphi[N_TOK * HALF],  g_tplo[N_TOK * HALF];
__device__ __nv_bfloat16 g_g2hi[N_TOK * HALF],  g_g2lo[N_TOK * HALF];
__device__ __nv_bfloat16 g_swhi[N_TOK * N_TOK], g_swlo[N_TOK * N_TOK];
__device__ __nv_bfloat16 g_bhi [4 * 1024 * 1024], g_blo[4 * 1024 * 1024];

// ---------------------------------------------------------------------------
// Helpers
// ---------------------------------------------------------------------------
__device__ __forceinline__ float gelu_f(float x) {
    const float c = 0.7978845608028654f;
    float t = tanhf(c * (x + 0.044715f * x * x * x));
    return 0.5f * x * (1.0f + t);
}

__device__ __forceinline__ uint32_t s2u(const void* p) {
    uint32_t a;
    asm("{ .reg .u64 t; cvta.to.shared.u64 t, %1; cvt.u32.u64 %0, t; }"
        : "=r"(a) : "l"(p));
    return a;
}

#define CP_ASYNC16(dst, src) \
    asm volatile("cp.async.cg.shared.global [%0], [%1], 16;" :: "r"(dst), "l"(src))
#define CP_COMMIT() asm volatile("cp.async.commit_group;" ::: "memory")
#define CP_WAIT0()  asm volatile("cp.async.wait_group 0;" ::: "memory")

#define LDSM4(r, addr) \
    asm volatile("ldmatrix.sync.aligned.m8n8.x4.shared.b16 {%0,%1,%2,%3}, [%4];" \
                 : "=r"((r)[0]), "=r"((r)[1]), "=r"((r)[2]), "=r"((r)[3]) : "r"(addr))

#define LDSM4T(r, addr) \
    asm volatile("ldmatrix.sync.aligned.m8n8.x4.trans.shared.b16 {%0,%1,%2,%3}, [%4];" \
                 : "=r"((r)[0]), "=r"((r)[1]), "=r"((r)[2]), "=r"((r)[3]) : "r"(addr))

__device__ __forceinline__ void mma_bf16(float* c, const uint32_t* a, const uint32_t* b) {
    asm volatile(
        "mma.sync.aligned.m16n8k16.row.col.f32.bf16.bf16.f32 "
        "{%0,%1,%2,%3}, {%4,%5,%6,%7}, {%8,%9}, {%0,%1,%2,%3};"
        : "+f"(c[0]), "+f"(c[1]), "+f"(c[2]), "+f"(c[3])
        : "r"(a[0]), "r"(a[1]), "r"(a[2]), "r"(a[3]), "r"(b[0]), "r"(b[1]));
}

__device__ __forceinline__ uint32_t pack_bf2(float a, float b) {
    __nv_bfloat162 h = __floats2bfloat162_rn(a, b);
    return *(uint32_t*)&h;
}
__device__ __forceinline__ float bf16r(float v) {
    return __bfloat162float(__float2bfloat16(v));
}

// ---------------------------------------------------------------------------
// Embedding gather
// ---------------------------------------------------------------------------
__global__ void embed_kernel(const int* __restrict__ tok,
                             const float* __restrict__ emb,
                             float* __restrict__ x) {
    int row = blockIdx.x;
    int t = tok[row];
    const float4* src = (const float4*)(emb + (size_t)t * DIM);
    float4* dst = (float4*)(x + (size_t)row * DIM);
    for (int i = threadIdx.x; i < DIM / 4; i += blockDim.x) dst[i] = src[i];
}

// ---------------------------------------------------------------------------
// LayerNorm: optional fp32 out and/or bf16 hi/lo out. float4 path.
// ---------------------------------------------------------------------------
__global__ void __launch_bounds__(256) ln_kernel(const float* __restrict__ src, int lds,
                                                 const float* __restrict__ gamma,
                                                 float* __restrict__ dstF,
                                                 __nv_bfloat16* __restrict__ hi,
                                                 __nv_bfloat16* __restrict__ lo,
                                                 int ldd, int D) {
    int row = blockIdx.x;
    const float* x = src + (size_t)row * lds;
    float s = 0.f, s2 = 0.f;
    for (int i = threadIdx.x * 4; i < D; i += 1024) {
        float4 v = *(const float4*)(x + i);
        s  += v.x + v.y + v.z + v.w;
        s2 += v.x * v.x + v.y * v.y + v.z * v.z + v.w * v.w;
    }
    __shared__ float sh[64];
    #pragma unroll
    for (int o = 16; o; o >>= 1) {
        s  += __shfl_xor_sync(0xFFFFFFFFu, s,  o);
        s2 += __shfl_xor_sync(0xFFFFFFFFu, s2, o);
    }
    int warp = threadIdx.x >> 5, lane = threadIdx.x & 31;
    if (lane == 0) { sh[warp] = s; sh[32 + warp] = s2; }
    __syncthreads();
    if (warp == 0) {
        s  = (lane < 8) ? sh[lane]      : 0.f;
        s2 = (lane < 8) ? sh[32 + lane] : 0.f;
        #pragma unroll
        for (int o = 4; o; o >>= 1) {
            s  += __shfl_xor_sync(0xFFFFFFFFu, s,  o);
            s2 += __shfl_xor_sync(0xFFFFFFFFu, s2, o);
        }
        if (lane == 0) {
            float mean = s / D;
            float var  = s2 / D - mean * mean;
            sh[0] = mean;
            sh[1] = rsqrtf(var + 1e-5f);
        }
    }
    __syncthreads();
    float mean = sh[0], rstd = sh[1];
    for (int i = threadIdx.x * 4; i < D; i += 1024) {
        float4 v = *(const float4*)(x + i);
        float4 g = *(const float4*)(gamma + i);
        float v0 = (v.x - mean) * rstd * g.x;
        float v1 = (v.y - mean) * rstd * g.y;
        float v2 = (v.z - mean) * rstd * g.z;
        float v3 = (v.w - mean) * rstd * g.w;
        size_t o = (size_t)row * ldd + i;
        if (dstF) {
            float4 w; w.x = v0; w.y = v1; w.z = v2; w.w = v3;
            *(float4*)(dstF + o) = w;
        }
        if (hi) {
            float h0 = bf16r(v0), h1 = bf16r(v1), h2 = bf16r(v2), h3 = bf16r(v3);
            uint2 uh, ul;
            uh.x = pack_bf2(h0, h1); uh.y = pack_bf2(h2, h3);
            ul.x = pack_bf2(v0 - h0, v1 - h1); ul.y = pack_bf2(v2 - h2, v3 - h3);
            *(uint2*)(hi + o) = uh;
            *(uint2*)(lo + o) = ul;
        }
    }
}

// ---------------------------------------------------------------------------
// Split A (fp32 -> bf16 hi/lo) with tril mask — only used for g_sw.
// ---------------------------------------------------------------------------
__global__ void __launch_bounds__(256) splitA_k(const float* __restrict__ A,
                                                __nv_bfloat16* __restrict__ hi,
                                                __nv_bfloat16* __restrict__ lo,
                                                int MK, int K, int tril) {
    int i4 = (blockIdx.x * 256 + threadIdx.x) * 4;
    if (i4 >= MK) return;
    float4 v = *(const float4*)(A + i4);
    float vv[4] = {v.x, v.y, v.z, v.w};
    if (tril) {
        int m = i4 / K, k = i4 - m * K;
        #pragma unroll
        for (int e = 0; e < 4; e++)
            if (k + e > m) vv[e] = 0.f;
    }
    float hf[4];
    #pragma unroll
    for (int e = 0; e < 4; e++) hf[e] = bf16r(vv[e]);
    uint2 ho, lo2;
    ho.x  = pack_bf2(hf[0], hf[1]); ho.y  = pack_bf2(hf[2], hf[3]);
    lo2.x = pack_bf2(vv[0] - hf[0], vv[1] - hf[1]);
    lo2.y = pack_bf2(vv[2] - hf[2], vv[3] - hf[3]);
    *(uint2*)(hi + i4) = ho;
    *(uint2*)(lo + i4) = lo2;
}

// ---------------------------------------------------------------------------
// Transpose + split B: B[K][N] fp32 -> Bt hi/lo bf16 [N][K]
// ---------------------------------------------------------------------------
__global__ void __launch_bounds__(256) tspB_k(const float* __restrict__ B,
                                              __nv_bfloat16* __restrict__ hi,
                                              __nv_bfloat16* __restrict__ lo,
                                              int K, int N) {
    __shared__ float sh[32][33];
    int nt = blockIdx.x * 32, kt = blockIdx.y * 32;
    int tx = threadIdx.x & 31, ty = threadIdx.x >> 5;
    #pragma unroll
    for (int j = 0; j < 32; j += 8)
        sh[ty + j][tx] = B[(size_t)(kt + ty + j) * N + nt + tx];
    __syncthreads();
    #pragma unroll
    for (int j = 0; j < 32; j += 8) {
        float v = sh[tx][ty + j];
        float h = bf16r(v);
        size_t o = (size_t)(nt + ty + j) * K + kt + tx;
        hi[o] = __float2bfloat16(h);
        lo[o] = __float2bfloat16(v - h);
    }
}

// ---------------------------------------------------------------------------
// Split-bf16 3-term tensor-core GEMM, templated on (BM, BK).
// BM=64 uses BK=64 (144B rows); BM=128 uses BK=32 (80B rows). 2 CTAs/SM.
// Single-sync mainloop; F_NOC skips dead fp32 C store.
// ---------------------------------------------------------------------------
enum { F_BIAS = 1, F_GELU = 2, F_RES = 4, F_MULX = 16, F_ROWB = 32, F_SPLIT = 64,
       F_NOC = 128 };

template <int FLAGS, int BM>
__global__ void __launch_bounds__(256, 2) gemm_bf3(
    const __nv_bfloat16* __restrict__ Ahi, const __nv_bfloat16* __restrict__ Alo,
    const __nv_bfloat16* __restrict__ Bhi, const __nv_bfloat16* __restrict__ Blo,
    const float* __restrict__ bias, const float* __restrict__ rbias,
    const float* __restrict__ Xm, int ldx,
    const float* __restrict__ resid,
    float* __restrict__ C,
    __nv_bfloat16* __restrict__ Chi, __nv_bfloat16* __restrict__ Clo,
    int M, int N, int K) {

    constexpr int BK    = (BM == 64) ? 64 : 32;
    constexpr int KROW  = BK * 2 + 16;
    constexpr int ATILE = BM * KROW;
    constexpr int BTILE = 128 * KROW;
    constexpr int STAGE = 2 * ATILE + 2 * BTILE;
    constexpr int UP    = (BM == 128) ? 4 : 2;
    constexpr int CHR   = BK / 8;
    constexpr int NKS   = BK / 16;

    extern __shared__ char dsm[];
    const uint32_t smem_base = s2u(dsm);

    const int tid  = threadIdx.x;
    const int wid  = tid >> 5;
    const int lane = tid & 31;
    const int wm   = (BM == 128) ? (wid >> 1) : (wid & 1);
    const int wn   = (BM == 128) ? (wid & 1)  : (wid >> 1);
    const int bm = blockIdx.y * BM, bn = blockIdx.x * 128;

    float acc[2][2 * UP][4];
    #pragma unroll
    for (int i = 0; i < 2; i++)
        #pragma unroll
        for (int j = 0; j < 2 * UP; j++)
            #pragma unroll
            for (int e = 0; e < 4; e++) acc[i][j][e] = 0.f;

    const __nv_bfloat16* bases[4] = {
        Ahi + (size_t)bm * K, Alo + (size_t)bm * K,
        Bhi + (size_t)bn * K, Blo + (size_t)bn * K };

    const int mi  = lane >> 3;
    const int lr8 = lane & 7;
    const int a_off = ((mi & 1) * 8 + lr8) * KROW + (mi >> 1) * 16;
    const int b_off = ((mi >> 1) * 8 + lr8) * KROW + (mi & 1) * 16;

    const int nK = K / BK;

    #define LOAD_STAGE(s, kt) do {                                             \
        uint32_t sb_ = smem_base + (s) * STAGE;                                \
        int kc_ = (kt) * BK;                                                   \
        _Pragma("unroll")                                                      \
        for (int t = 0; t < 2 * BM * CHR / 256; t++) {                         \
            int w = t * 256 + tid;                                             \
            int tile = w / (BM * CHR);                                         \
            int rr = (w % (BM * CHR)) / CHR, ch = w % CHR;                     \
            const char* src = (const char*)(bases[tile] + (size_t)rr * K + kc_ + ch * 8); \
            uint32_t dst = sb_ + tile * ATILE + rr * KROW + ch * 16;           \
            CP_ASYNC16(dst, src);                                              \
        }                                                                      \
        _Pragma("unroll")                                                      \
        for (int t = 0; t < 2 * 128 * CHR / 256; t++) {                        \
            int w = t * 256 + tid;                                             \
            int bt = w / (128 * CHR);                                          \
            int rr = (w % (128 * CHR)) / CHR, ch = w % CHR;                    \
            const char* src = (const char*)(bases[2 + bt] + (size_t)rr * K + kc_ + ch * 8); \
            uint32_t dst = sb_ + 2 * ATILE + bt * BTILE + rr * KROW + ch * 16; \
            CP_ASYNC16(dst, src);                                              \
        }                                                                      \
        CP_COMMIT();                                                           \
    } while (0)

    LOAD_STAGE(0, 0);

    for (int kt = 0; kt < nK; kt++) {
        int s = kt & 1;
        CP_WAIT0();
        __syncthreads();
        if (kt + 1 < nK) LOAD_STAGE(s ^ 1, kt + 1);

        uint32_t TAh = smem_base + s * STAGE;
        uint32_t TAl = TAh + ATILE;
        uint32_t TBh = TAh + 2 * ATILE;
        uint32_t TBl = TBh + BTILE;

        #pragma unroll
        for (int ks = 0; ks < NKS; ks++) {
            uint32_t ah[2][4], al_[2][4];
            #pragma unroll
            for (int mt = 0; mt < 2; mt++) {
                int rb = (wm * 32 + mt * 16) * KROW + ks * 32;
                LDSM4(ah[mt],  TAh + rb + a_off);
                LDSM4(al_[mt], TAl + rb + a_off);
            }
            uint32_t bh[UP][4], bl[UP][4];
            #pragma unroll
            for (int up = 0; up < UP; up++) {
                int rb = (wn * UP * 16 + up * 16) * KROW + ks * 32;
                LDSM4(bh[up], TBh + rb + b_off);
                LDSM4(bl[up], TBl + rb + b_off);
            }
            #pragma unroll
            for (int term = 0; term < 3; term++) {
                #pragma unroll
                for (int mt = 0; mt < 2; mt++) {
                    const uint32_t* A_ = (term == 2) ? al_[mt] : ah[mt];
                    #pragma unroll
                    for (int up = 0; up < UP; up++) {
                        const uint32_t* B_ = (term == 1) ? bl[up] : bh[up];
                        mma_bf16(acc[mt][2 * up],     A_, &B_[0]);
                        mma_bf16(acc[mt][2 * up + 1], A_, &B_[2]);
                    }
                }
            }
        }
    }

    const int r0 = bm + wm * 32 + (lane >> 2);
    const int cb = bn + wn * (UP * 16) + (lane & 3) * 2;
    #pragma unroll
    for (int mt = 0; mt < 2; mt++) {
        #pragma unroll
        for (int nt = 0; nt < 2 * UP; nt++) {
            float* a4 = acc[mt][nt];
            int gm = r0 + mt * 16;
            int gn = cb + nt * 8;
            float vv[4];
            #pragma unroll
            for (int e = 0; e < 4; e++) {
                int rr = gm + (e >> 1) * 8;
                int cc = gn + (e & 1);
                float v = a4[e];
                if (FLAGS & F_BIAS) v += bias[cc];
                if (FLAGS & F_ROWB) v += rbias[rr];
                if (FLAGS & F_GELU) v = gelu_f(v);
                if (FLAGS & F_MULX) v *= Xm[(size_t)rr * ldx + cc];
                if (FLAGS & F_RES)  v += resid[(size_t)rr * N + cc];
                vv[e] = v;
            }
            size_t o0 = (size_t)gm * N + gn;
            size_t o1 = (size_t)(gm + 8) * N + gn;
            if (!(FLAGS & F_NOC)) {
                *(float2*)(C + o0) = make_float2(vv[0], vv[1]);
                *(float2*)(C + o1) = make_float2(vv[2], vv[3]);
            }
            if (FLAGS & F_SPLIT) {
                float h0 = bf16r(vv[0]), h1 = bf16r(vv[1]);
                float h2 = bf16r(vv[2]), h3 = bf16r(vv[3]);
                *(uint32_t*)(Chi + o0) = pack_bf2(h0, h1);
                *(uint32_t*)(Chi + o1) = pack_bf2(h2, h3);
                *(uint32_t*)(Clo + o0) = pack_bf2(vv[0] - h0, vv[1] - h1);
                *(uint32_t*)(Clo + o1) = pack_bf2(vv[2] - h2, vv[3] - h3);
            }
        }
    }
}

// ---------------------------------------------------------------------------
// Exact fp32 SIMT GEMM for the head (N=32): 64 CTAs x 32 rows, 4 cols/thread.
// K-order accumulation identical to previous version (bitwise-same output).
// ---------------------------------------------------------------------------
__global__ void __launch_bounds__(256) gemm_head(
    const float* __restrict__ A, const float* __restrict__ B,
    const float* __restrict__ bias, float* __restrict__ C,
    int M, int N, int K) {
    __shared__ float As[16][32];
    __shared__ float Bs[16][32];
    const int tid = threadIdx.x;
    const int bm = blockIdx.y * 32;
    const int r  = tid >> 3;          // 0..31
    const int cp = (tid & 7) * 4;     // 0..28
    float acc[4] = {0.f, 0.f, 0.f, 0.f};

    const int a_row = tid >> 3, a_col = (tid & 7) * 2;   // 32 rows x 16 k-cols
    const int b_row = tid >> 4, b_col = (tid & 15) * 2;  // 16 k-rows x 32 cols

    for (int kt = 0; kt < K; kt += 16) {
        float2 va = *(const float2*)(A + (size_t)(bm + a_row) * K + kt + a_col);
        As[a_col][a_row]     = va.x;
        As[a_col + 1][a_row] = va.y;
        float2 vb = *(const float2*)(B + (size_t)(kt + b_row) * N + b_col);
        Bs[b_row][b_col]     = vb.x;
        Bs[b_row][b_col + 1] = vb.y;
        __syncthreads();
        #pragma unroll
        for (int kk = 0; kk < 16; kk++) {
            float a = As[kk][r];
            #pragma unroll
            for (int j = 0; j < 4; j++) acc[j] += a * Bs[kk][cp + j];
        }
        __syncthreads();
    }
    #pragma unroll
    for (int j = 0; j < 4; j++)
        C[(size_t)(bm + r) * N + cp + j] = acc[j] + bias[cp + j];
}

// ---------------------------------------------------------------------------
// Tensor-core flash attention (round-14 winner, unchanged).
// ---------------------------------------------------------------------------
#define AQH 0
#define AQL 9216
#define AKH 18432
#define AKL 27648
#define AVH 36864
#define AVL 46080
#define ATT_SMEM 55296

__global__ void __launch_bounds__(128, 3) attn_tc(const float* __restrict__ qkv,
                                                  __nv_bfloat16* __restrict__ athi,
                                                  __nv_bfloat16* __restrict__ atlo) {
    extern __shared__ char dsm[];
    const uint32_t sb = s2u(dsm);

    const int h  = blockIdx.z;
    const int w  = blockIdx.y;
    const int qt = blockIdx.x;
    const int tid  = threadIdx.x;
    const int wm   = tid >> 5;
    const int lane = tid & 31;
    const int mi   = lane >> 3;
    const int lr8  = lane & 7;

    {
        int row = tid >> 1, halfd = tid & 1;
        int tq = w * WSZ + qt * 64 + row;
        const float4* qp = (const float4*)(qkv + (size_t)tq * (3 * INNER) + h * DHEAD + halfd * 32);
        char* dh = dsm + AQH + row * 144 + halfd * 64;
        char* dl = dsm + AQL + row * 144 + halfd * 64;
        #pragma unroll
        for (int f = 0; f < 8; f++) {
            float4 v = qp[f];
            float a0 = v.x * 0.125f, a1 = v.y * 0.125f, a2 = v.z * 0.125f, a3 = v.w * 0.125f;
            float h0 = bf16r(a0), h1 = bf16r(a1), h2 = bf16r(a2), h3 = bf16r(a3);
            uint2 uh, ul;
            uh.x = pack_bf2(h0, h1); uh.y = pack_bf2(h2, h3);
            ul.x = pack_bf2(a0 - h0, a1 - h1); ul.y = pack_bf2(a2 - h2, a3 - h3);
            *(uint2*)(dh + f * 8) = uh;
            *(uint2*)(dl + f * 8) = ul;
        }
    }
    __syncthreads();

    uint32_t qf_h[4][4], qf_l[4][4];
    {
        uint32_t abase = sb + (wm * 16 + (mi & 1) * 8 + lr8) * 144 + (mi >> 1) * 16;
        #pragma unroll
        for (int ks = 0; ks < 4; ks++) {
            LDSM4(qf_h[ks], abase + AQH + ks * 32);
            LDSM4(qf_l[ks], abase + AQL + ks * 32);
        }
    }

    float Oacc[8][4];
    #pragma unroll
    for (int nt = 0; nt < 8; nt++)
        #pragma unroll
        for (int e = 0; e < 4; e++) Oacc[nt][e] = 0.f;
    float mrow[2] = {-1e30f, -1e30f};
    float lrow[2] = {0.f, 0.f};

    const int i_base = qt * 64 + wm * 16 + (lane >> 2);
    const int nchunk = qt + 9;

    const uint32_t boffKV = ((mi >> 1) * 8 + lr8) * 144 + (mi & 1) * 16;
    const uint32_t toffV  = ((mi & 1) * 8 + lr8) * 144 + (mi >> 1) * 16;

    for (int c = 0; c < nchunk; c++) {
        int j0 = c * 64;
        __syncthreads();

        {
            int row = tid >> 1, halfd = tid & 1;
            int tk = (w - 1) * WSZ + j0 + row;
            const float4* kp = (const float4*)(qkv + (size_t)tk * (3 * INNER) + INNER + h * DHEAD + halfd * 32);
            const float4* vp = kp + INNER / 4;
            char* dkh = dsm + AKH + row * 144 + halfd * 64;
            char* dkl = dsm + AKL + row * 144 + halfd * 64;
            char* dvh = dsm + AVH + row * 144 + halfd * 64;
            char* dvl = dsm + AVL + row * 144 + halfd * 64;
            #pragma unroll
            for (int f = 0; f < 8; f++) {
                float4 kv = make_float4(0.f, 0.f, 0.f, 0.f);
                float4 vv = make_float4(0.f, 0.f, 0.f, 0.f);
                if (tk >= 0) { kv = kp[f]; vv = vp[f]; }
                float kh0 = bf16r(kv.x), kh1 = bf16r(kv.y), kh2 = bf16r(kv.z), kh3 = bf16r(kv.w);
                float vh0 = bf16r(vv.x), vh1 = bf16r(vv.y), vh2 = bf16r(vv.z), vh3 = bf16r(vv.w);
                uint2 u;
                u.x = pack_bf2(kh0, kh1); u.y = pack_bf2(kh2, kh3);
                *(uint2*)(dkh + f * 8) = u;
                u.x = pack_bf2(kv.x - kh0, kv.y - kh1); u.y = pack_bf2(kv.z - kh2, kv.w - kh3);
                *(uint2*)(dkl + f * 8) = u;
                u.x = pack_bf2(vh0, vh1); u.y = pack_bf2(vh2, vh3);
                *(uint2*)(dvh + f * 8) = u;
                u.x = pack_bf2(vv.x - vh0, vv.y - vh1); u.y = pack_bf2(vv.z - vh2, vv.w - vh3);
                *(uint2*)(dvl + f * 8) = u;
            }
        }
        __syncthreads();

        float Sa[8][4];
        #pragma unroll
        for (int nt = 0; nt < 8; nt++)
            #pragma unroll
            for (int e = 0; e < 4; e++) Sa[nt][e] = 0.f;

        #pragma unroll
        for (int ks = 0; ks < 4; ks++) {
            #pragma unroll
            for (int ng = 0; ng < 4; ng++) {
                uint32_t kb = sb + (ng * 16) * 144 + boffKV + ks * 32;
                uint32_t kh4[4], kl4[4];
                LDSM4(kh4, kb + AKH);
                LDSM4(kl4, kb + AKL);
                mma_bf16(Sa[2 * ng],     qf_h[ks], &kh4[0]);
                mma_bf16(Sa[2 * ng],     qf_h[ks], &kl4[0]);
                mma_bf16(Sa[2 * ng],     qf_l[ks], &kh4[0]);
                mma_bf16(Sa[2 * ng + 1], qf_h[ks], &kh4[2]);
                mma_bf16(Sa[2 * ng + 1], qf_h[ks], &kl4[2]);
                mma_bf16(Sa[2 * ng + 1], qf_l[ks], &kh4[2]);
            }
        }

        #pragma unroll
        for (int nt = 0; nt < 8; nt++)
            #pragma unroll
            for (int e = 0; e < 4; e++) {
                int col = j0 + nt * 8 + (lane & 3) * 2 + (e & 1);
                int ri  = i_base + (e >> 1) * 8;
                if (col > ri + WSZ) Sa[nt][e] = -1e30f;
            }

        #pragma unroll
        for (int e2 = 0; e2 < 2; e2++) {
            float mx = -1e30f;
            #pragma unroll
            for (int nt = 0; nt < 8; nt++) {
                mx = fmaxf(mx, Sa[nt][e2 * 2]);
                mx = fmaxf(mx, Sa[nt][e2 * 2 + 1]);
            }
            mx = fmaxf(mx, __shfl_xor_sync(0xFFFFFFFFu, mx, 1));
            mx = fmaxf(mx, __shfl_xor_sync(0xFFFFFFFFu, mx, 2));
            float mnew = fmaxf(mrow[e2], mx);
            float corr = __expf(mrow[e2] - mnew);
            mrow[e2] = mnew;
            lrow[e2] *= corr;
            #pragma unroll
            for (int nt = 0; nt < 8; nt++) {
                Oacc[nt][e2 * 2]     *= corr;
                Oacc[nt][e2 * 2 + 1] *= corr;
            }
            float psum = 0.f;
            #pragma unroll
            for (int nt = 0; nt < 8; nt++) {
                float p0 = __expf(Sa[nt][e2 * 2]     - mnew);
                float p1 = __expf(Sa[nt][e2 * 2 + 1] - mnew);
                Sa[nt][e2 * 2]     = p0;
                Sa[nt][e2 * 2 + 1] = p1;
                psum += p0 + p1;
            }
            lrow[e2] += psum;
        }

        #pragma unroll
        for (int kt = 0; kt < 4; kt++) {
            uint32_t ph[4], pl[4];
            #pragma unroll
            for (int half = 0; half < 2; half++) {
                float s0 = Sa[2 * kt + half][0], s1 = Sa[2 * kt + half][1];
                float s2 = Sa[2 * kt + half][2], s3 = Sa[2 * kt + half][3];
                float h0 = bf16r(s0), h1 = bf16r(s1), h2 = bf16r(s2), h3 = bf16r(s3);
                ph[2 * half]     = pack_bf2(h0, h1);
                ph[2 * half + 1] = pack_bf2(h2, h3);
                pl[2 * half]     = pack_bf2(s0 - h0, s1 - h1);
                pl[2 * half + 1] = pack_bf2(s2 - h2, s3 - h3);
            }
            #pragma unroll
            for (int vt = 0; vt < 4; vt++) {
                uint32_t vb = sb + (kt * 16) * 144 + toffV + vt * 32;
                uint32_t vh4[4], vl4[4];
                LDSM4T(vh4, vb + AVH);
                LDSM4T(vl4, vb + AVL);
                mma_bf16(Oacc[2 * vt],     ph, &vh4[0]);
                mma_bf16(Oacc[2 * vt],     pl, &vh4[0]);
                mma_bf16(Oacc[2 * vt],     ph, &vl4[0]);
                mma_bf16(Oacc[2 * vt + 1], ph, &vh4[2]);
                mma_bf16(Oacc[2 * vt + 1], pl, &vh4[2]);
                mma_bf16(Oacc[2 * vt + 1], ph, &vl4[2]);
            }
        }
    }

    float inv[2];
    #pragma unroll
    for (int e2 = 0; e2 < 2; e2++) {
        float l = lrow[e2];
        l += __shfl_xor_sync(0xFFFFFFFFu, l, 1);
        l += __shfl_xor_sync(0xFFFFFFFFu, l, 2);
        inv[e2] = 1.f / l;
    }
    const int tok0 = w * WSZ + qt * 64 + wm * 16 + (lane >> 2);
    const int cb   = h * DHEAD + (lane & 3) * 2;
    #pragma unroll
    for (int nt = 0; nt < 8; nt++) {
        #pragma unroll
        for (int e2 = 0; e2 < 2; e2++) {
            int tok = tok0 + e2 * 8;
            float a = Oacc[nt][e2 * 2]     * inv[e2];
            float b = Oacc[nt][e2 * 2 + 1] * inv[e2];
            float ha = bf16r(a), hb = bf16r(b);
            size_t o = (size_t)tok * INNER + cb + nt * 8;
            *(uint32_t*)(athi + o) = pack_bf2(ha, hb);
            *(uint32_t*)(atlo + o) = pack_bf2(a - ha, b - hb);
        }
    }
}

// ---------------------------------------------------------------------------
// Host-side dispatch
// ---------------------------------------------------------------------------
static __nv_bfloat16 *BHI, *BLO;

#define SMEM64  (2 * (2 * 64 * 144 + 2 * 128 * 144))   // 110592
#define SMEM128 (2 * (2 * 128 * 80 + 2 * 128 * 80))    // 81920

static void gemm(int flags, const __nv_bfloat16* Ahi, const __nv_bfloat16* Alo,
                 const float* B, const float* bias, const float* rbias,
                 const float* Xm, int ldx, const float* resid,
                 float* C, __nv_bfloat16* Chi, __nv_bfloat16* Clo,
                 int M, int N, int K) {
    tspB_k<<<dim3(N / 32, K / 32), 256>>>(B, BHI, BLO, K, N);
    if (N <= 1536) {
        dim3 grid(N / 128, M / 64);
        switch (flags) {
            case 0:
                gemm_bf3<0, 64><<<grid, 256, SMEM64>>>(Ahi, Alo, BHI, BLO, bias, rbias, Xm, ldx, resid, C, Chi, Clo, M, N, K); break;
            case F_BIAS | F_RES:
                gemm_bf3<F_BIAS | F_RES, 64><<<grid, 256, SMEM64>>>(Ahi, Alo, BHI, BLO, bias, rbias, Xm, ldx, resid, C, Chi, Clo, M, N, K); break;
        }
    } else {
        dim3 grid(N / 128, M / 128);
        switch (flags) {
            case F_BIAS | F_GELU:
                gemm_bf3<F_BIAS | F_GELU, 128><<<grid, 256, SMEM128>>>(Ahi, Alo, BHI, BLO, bias, rbias, Xm, ldx, resid, C, Chi, Clo, M, N, K); break;
            case F_BIAS | F_GELU | F_SPLIT | F_NOC:
                gemm_bf3<F_BIAS | F_GELU | F_SPLIT | F_NOC, 128><<<grid, 256, SMEM128>>>(Ahi, Alo, BHI, BLO, bias, rbias, Xm, ldx, resid, C, Chi, Clo, M, N, K); break;
            case F_ROWB | F_MULX | F_SPLIT | F_NOC:
                gemm_bf3<F_ROWB | F_MULX | F_SPLIT | F_NOC, 128><<<grid, 256, SMEM128>>>(Ahi, Alo, BHI, BLO, bias, rbias, Xm, ldx, resid, C, Chi, Clo, M, N, K); break;
            case F_BIAS | F_SPLIT | F_NOC:
                gemm_bf3<F_BIAS | F_SPLIT | F_NOC, 128><<<grid, 256, SMEM128>>>(Ahi, Alo, BHI, BLO, bias, rbias, Xm, ldx, resid, C, Chi, Clo, M, N, K); break;
        }
    }
}

extern "C" void kernel_launch(void* const* d_in, const int* in_sizes, int n_in,
                              void* d_out, int out_size) {
    (void)in_sizes; (void)n_in;
    const int*   tokens   = (const int*)  d_in[0];
    const float* embed    = (const float*)d_in[1];
    const float* attn_ln  = (const float*)d_in[2];
    const float* attn_qkv = (const float*)d_in[3];
    const float* attn_ow  = (const float*)d_in[4];
    const float* attn_ob  = (const float*)d_in[5];
    const float* ff_ln    = (const float*)d_in[6];
    const float* ff_w1    = (const float*)d_in[7];
    const float* ff_b1    = (const float*)d_in[8];
    const float* ff_w2    = (const float*)d_in[9];
    const float* ff_b2    = (const float*)d_in[10];
    const float* gl_ln    = (const float*)d_in[11];
    const float* g_win    = (const float*)d_in[12];
    const float* g_bin    = (const float*)d_in[13];
    const float* g_sln    = (const float*)d_in[14];
    const float* g_sw     = (const float*)d_in[15];
    const float* g_sb     = (const float*)d_in[16];
    const float* g_sow    = (const float*)d_in[17];
    const float* g_sob    = (const float*)d_in[18];
    const float* g_pow    = (const float*)d_in[19];
    const float* g_pob    = (const float*)d_in[20];
    const float* fin_ln   = (const float*)d_in[21];
    const float* head_w   = (const float*)d_in[22];
    const float* head_b   = (const float*)d_in[23];
    float* out = (float*)d_out;
    (void)out_size;

    float *X, *XN, *QKV, *H, *GT, *TP;
    __nv_bfloat16 *XNHI, *XNLO, *HHI, *HLO, *ATHI, *ATLO, *TPHI, *TPLO,
                  *G2HI, *G2LO, *SWHI, *SWLO;
    cudaGetSymbolAddress((void**)&X,    g_x);
    cudaGetSymbolAddress((void**)&XN,   g_xn);
    cudaGetSymbolAddress((void**)&QKV,  g_qkv);
    cudaGetSymbolAddress((void**)&H,    g_h);
    cudaGetSymbolAddress((void**)&GT,   g_gt);
    cudaGetSymbolAddress((void**)&TP,   g_tp);
    cudaGetSymbolAddress((void**)&XNHI, g_xnhi);
    cudaGetSymbolAddress((void**)&XNLO, g_xnlo);
    cudaGetSymbolAddress((void**)&HHI,  g_hhi);
    cudaGetSymbolAddress((void**)&HLO,  g_hlo);
    cudaGetSymbolAddress((void**)&ATHI, g_athi);
    cudaGetSymbolAddress((void**)&ATLO, g_atlo);
    cudaGetSymbolAddress((void**)&TPHI, g_tphi);
    cudaGetSymbolAddress((void**)&TPLO, g_tplo);
    cudaGetSymbolAddress((void**)&G2HI, g_g2hi);
    cudaGetSymbolAddress((void**)&G2LO, g_g2lo);
    cudaGetSymbolAddress((void**)&SWHI, g_swhi);
    cudaGetSymbolAddress((void**)&SWLO, g_swlo);
    cudaGetSymbolAddress((void**)&BHI,  g_bhi);
    cudaGetSymbolAddress((void**)&BLO,  g_blo);

    cudaFuncSetAttribute((const void*)gemm_bf3<0, 64>, cudaFuncAttributeMaxDynamicSharedMemorySize, SMEM64);
    cudaFuncSetAttribute((const void*)gemm_bf3<F_BIAS | F_RES, 64>, cudaFuncAttributeMaxDynamicSharedMemorySize, SMEM64);
    cudaFuncSetAttribute((const void*)gemm_bf3<F_BIAS | F_GELU, 128>, cudaFuncAttributeMaxDynamicSharedMemorySize, SMEM128);
    cudaFuncSetAttribute((const void*)gemm_bf3<F_BIAS | F_GELU | F_SPLIT | F_NOC, 128>, cudaFuncAttributeMaxDynamicSharedMemorySize, SMEM128);
    cudaFuncSetAttribute((const void*)gemm_bf3<F_ROWB | F_MULX | F_SPLIT | F_NOC, 128>, cudaFuncAttributeMaxDynamicSharedMemorySize, SMEM128);
    cudaFuncSetAttribute((const void*)gemm_bf3<F_BIAS | F_SPLIT | F_NOC, 128>, cudaFuncAttributeMaxDynamicSharedMemorySize, SMEM128);
    cudaFuncSetAttribute((const void*)attn_tc, cudaFuncAttributeMaxDynamicSharedMemorySize, ATT_SMEM);

    embed_kernel<<<N_TOK, 256>>>(tokens, embed, X);

    for (int l = 0; l < DEPTH; l++) {
        const float* al = attn_ln  + (size_t)l * DIM;
        const float* aq = attn_qkv + (size_t)l * DIM * 3 * INNER;
        const float* aw = attn_ow  + (size_t)l * INNER * DIM;
        const float* ab = attn_ob  + (size_t)l * DIM;
        const float* fl = ff_ln    + (size_t)l * DIM;
        const float* f1 = ff_w1    + (size_t)l * DIM * DFF;
        const float* b1 = ff_b1    + (size_t)l * DFF;
        const float* f2 = ff_w2    + (size_t)l * DFF * DIM;
        const float* b2 = ff_b2    + (size_t)l * DIM;

        ln_kernel<<<N_TOK, 256>>>(X, DIM, al, nullptr, XNHI, XNLO, DIM, DIM);
        gemm(0, XNHI, XNLO, aq, nullptr, nullptr, nullptr, 0, nullptr,
             QKV, nullptr, nullptr, N_TOK, 3 * INNER, DIM);
        attn_tc<<<dim3(8, 4, NHEAD), 128, ATT_SMEM>>>(QKV, ATHI, ATLO);
        gemm(F_BIAS | F_RES, ATHI, ATLO, aw, ab, nullptr, nullptr, 0, X,
             X, nullptr, nullptr, N_TOK, DIM, INNER);

        ln_kernel<<<N_TOK, 256>>>(X, DIM, fl, nullptr, XNHI, XNLO, DIM, DIM);
        gemm(F_BIAS | F_GELU | F_SPLIT | F_NOC, XNHI, XNLO, f1, b1, nullptr, nullptr, 0, nullptr,
             H, HHI, HLO, N_TOK, DFF, DIM);
        gemm(F_BIAS | F_RES, HHI, HLO, f2, b2, nullptr, nullptr, 0, X,
             X, nullptr, nullptr, N_TOK, DIM, DFF);
    }

    for (int g = 0; g < GDEPTH; g++) {
        const float* gl  = gl_ln + (size_t)g * DIM;
        const float* wi  = g_win + (size_t)g * DIM * DFF;
        const float* bi  = g_bin + (size_t)g * DFF;
        const float* sl  = g_sln + (size_t)g * HALF;
        const float* sw  = g_sw  + (size_t)g * N_TOK * N_TOK;
        const float* sb  = g_sb  + (size_t)g * N_TOK;
        const float* so  = g_sow + (size_t)g * HALF * HALF;
        const float* sob = g_sob + (size_t)g * HALF;
        const float* po  = g_pow + (size_t)g * HALF * DIM;
        const float* pob = g_pob + (size_t)g * DIM;

        ln_kernel<<<N_TOK, 256>>>(X, DIM, gl, nullptr, XNHI, XNLO, DIM, DIM);
        gemm(F_BIAS | F_GELU, XNHI, XNLO, wi, bi, nullptr, nullptr, 0, nullptr,
             H, nullptr, nullptr, N_TOK, DFF, DIM);
        ln_kernel<<<N_TOK, 256>>>(H + HALF, DFF, sl, GT, nullptr, nullptr, HALF, HALF);
        splitA_k<<<(N_TOK * N_TOK / 4 + 255) / 256, 256>>>(sw, SWHI, SWLO,
                                                           N_TOK * N_TOK, N_TOK, 1);
        gemm(F_ROWB | F_MULX | F_SPLIT | F_NOC, SWHI, SWLO, GT, nullptr, sb, H, DFF, nullptr,
             TP, TPHI, TPLO, N_TOK, HALF, N_TOK);
        gemm(F_BIAS | F_SPLIT | F_NOC, TPHI, TPLO, so, sob, nullptr, nullptr, 0, nullptr,
             GT, G2HI, G2LO, N_TOK, HALF, HALF);
        gemm(F_BIAS | F_RES, G2HI, G2LO, po, pob, nullptr, nullptr, 0, X,
             X, nullptr, nullptr, N_TOK, DIM, HALF);
    }

    ln_kernel<<<N_TOK, 256>>>(X, DIM, fin_ln, XN, nullptr, nullptr, DIM, DIM);
    gemm_head<<<dim3(1, N_TOK / 32), 256>>>(XN, head_w, head_b, out, N_TOK, VOCAB, DIM);
}